// round 15
// baseline (speedup 1.0000x reference)
#include <cuda_runtime.h>

#define BB 16
#define NN 2048
#define KK 20
#define KC 26               // phase-A candidate count per subset (margin 6)
#define NEg (BB*NN*KK)      // 655360 edges
#define EPSV 1e-5f
#define NREP 32             // stats accumulator replication factor
#define NPTS (BB*NN)        // 32768 points
#define PTCH (NPTS*64)      // 2097152 entries per table

// ---------------- scratch (static device allocations) ----------------
__device__ float g_tab[12582912];         // enc max/min tables (4 x 2M) + plain pre tables (2 x 2M)
__device__ int   g_idx[NEg];
__device__ float g_scrS[NPTS*4*KC];       // knn phase-A scores (sorted desc per subset)
__device__ int   g_scrI[NPTS*4*KC];       // knn phase-A candidate indices
__device__ float g_x1[PTCH];
__device__ float g_x2[PTCH];
__device__ float g_x3[PTCH];
__device__ float g_Pa[PTCH];
__device__ float g_Pc[PTCH];
__device__ float g_sq[NPTS];
__device__ float g_ypre[33554432];        // B*N*1024
__device__ double g_accR[NREP*6*2048];    // replicated per-layer sum/sumsq
__device__ float g_scale[6*1024];
__device__ float g_shift[6*1024];

__device__ __forceinline__ unsigned fenc(float f){
    unsigned b = __float_as_uint(f);
    return (b>>31) ? ~b : (b | 0x80000000u);
}
__device__ __forceinline__ float fdec(unsigned e){
    unsigned b = (e>>31) ? (e ^ 0x80000000u) : ~e;
    return __uint_as_float(b);
}

__global__ void zero_acc_kernel() {
    int i = blockIdx.x*256 + threadIdx.x;
    if (i < NREP*6*2048) g_accR[i] = 0.0;
    unsigned* t = reinterpret_cast<unsigned*>(g_tab);
    for (int j = i; j < 4*PTCH; j += gridDim.x*256)
        t[j] = ((j>>21)&1) ? 0xFFFFFFFFu : 0u;
}

// squared norms from raw x (B,3,N)
__global__ void sqx_kernel(const float* __restrict__ x){
    int i = blockIdx.x*256 + threadIdx.x;
    if (i < NPTS){
        int b = i >> 11, n = i & (NN-1);
        const float* xb = x + (size_t)b*3*NN;
        float a=xb[n], c=xb[NN+n], d=xb[2*NN+n];
        g_sq[i] = a*a + c*c + d*d;
    }
}

// squared norms from 64-channel point features
__global__ void sq64_kernel(int sel){
    const float* pts = (sel==1) ? g_x1 : g_x2;
    int i = blockIdx.x*128 + threadIdx.x;
    if (i < NPTS){
        const float4* p = reinterpret_cast<const float4*>(pts + ((size_t)i<<6));
        float s = 0.f;
#pragma unroll
        for (int q=0;q<16;q++){
            float4 v = p[q];
            s += v.x*v.x + v.y*v.y + v.z*v.z + v.w*v.w;
        }
        g_sq[i] = s;
    }
}

// ---------------- KNN phase A: 4-way candidate split, fp32 top-26 per subset ----------------
template<int C>
__global__ void knn_part(const float* __restrict__ ext, int sel, int sB, int sN, int sC)
{
    const float* pts = (sel==0) ? ext : (sel==1 ? g_x1 : g_x2);
    __shared__ __align__(16) float tile[128][(C==3)?4:68];
    __shared__ float sqs[128];
    int b = blockIdx.z;
    int s = blockIdx.y;
    int row = blockIdx.x*128 + threadIdx.x;
    const float* base = pts + (size_t)b * sB;
    const float* sqb  = g_sq + (size_t)b * NN;

    float p[C];
#pragma unroll
    for (int c=0;c<C;c++) p[c] = base[(size_t)row*sN + (size_t)c*sC];

    float bd[KC]; int bi[KC];
#pragma unroll
    for (int i=0;i<KC;i++){ bd[i]=-3.4e38f; bi[i]=0; }
    float worst = -3.4e38f;

    int t0 = s*512;
    for (int t=t0; t<t0+512; t+=128) {
        __syncthreads();
        if (C==3) {
            for (int i=threadIdx.x;i<128*3;i+=128){
                int c=i>>7, col=i&127;
                tile[col][c] = base[(size_t)(t+col)*sN + (size_t)c*sC];
            }
        } else {
            const float4* b4 = reinterpret_cast<const float4*>(base);
            for (int i=threadIdx.x;i<128*(C/4);i+=128){
                int col=i>>4, cq=i&15;
                *reinterpret_cast<float4*>(&tile[col][cq<<2]) =
                    b4[((size_t)(t+col)<<4)+cq];
            }
        }
        sqs[threadIdx.x] = sqb[t+threadIdx.x];
        __syncthreads();
#pragma unroll 1
        for (int j=0;j<128;j++) {
            float d;
            if (C==3) {
                d = 2.f*(p[0]*tile[j][0]+p[1]*tile[j][1]+p[2]*tile[j][2]) - sqs[j];
            } else {
                float d0=0.f,d1=0.f,d2=0.f,d3=0.f;
#pragma unroll
                for (int cq=0;cq<C/4;cq++){
                    float4 tv = *reinterpret_cast<const float4*>(&tile[j][cq*4]);
                    d0 += p[cq*4+0]*tv.x; d1 += p[cq*4+1]*tv.y;
                    d2 += p[cq*4+2]*tv.z; d3 += p[cq*4+3]*tv.w;
                }
                d = 2.f*((d0+d1)+(d2+d3)) - sqs[j];
            }
            if (d > worst) {
                int jj = t + j;
                bool top = (bd[0] < d);
#pragma unroll
                for (int ss=KC-1; ss>=1; ss--){
                    float a    = bd[ss-1];
                    int   ai   = bi[ss-1];
                    float self = bd[ss];
                    bool shift = (a < d);
                    bool place = (!shift) && (self < d);
                    bd[ss] = place ? d  : (shift ? a  : self);
                    bi[ss] = place ? jj : (shift ? ai : bi[ss]);
                }
                if (top){ bd[0]=d; bi[0]=jj; }
                worst = bd[KC-1];
            }
        }
    }
    float* oS = g_scrS + ((size_t)(b*NN+row)*4 + s)*KC;
    int*   oI = g_scrI + ((size_t)(b*NN+row)*4 + s)*KC;
#pragma unroll
    for (int i=0;i<KC;i++){ oS[i]=bd[i]; oI[i]=bi[i]; }
}

// ---------------- KNN merge: rank union of 4 sorted lists, fp64 rerank -> top-20 set ----------------
template<int C>
__global__ void __launch_bounds__(256) knn_merge(const float* __restrict__ ext,
                                                 int sel, int sB, int sN, int sC)
{
    const float* pts = (sel==0) ? ext : (sel==1 ? g_x1 : g_x2);
    __shared__ float  sc[64][104];
    __shared__ int    ssel[64][26];
    __shared__ double dval[64][26];
    int tid = threadIdx.x;
    int s  = tid & 3;
    int ql = tid >> 2;
    int qg = blockIdx.x*64 + ql;
    int b  = qg >> 11;
    int row = qg & (NN-1);

    {
        const float* iS = g_scrS + ((size_t)qg*4 + s)*KC;
#pragma unroll
        for (int i=0;i<KC;i++) sc[ql][s*KC+i] = iS[i];
    }
    __syncthreads();

    // rank each own item within the 104-union (monotone 3-pointer walk)
    {
        int os0=(s+1)&3, os1=(s+2)&3, os2=(s+3)&3;
        bool g0 = os0<s, g1 = os1<s, g2 = os2<s;
        int q0=0,q1=0,q2=0;
#pragma unroll 1
        for (int i=0;i<KC;i++){
            float m = sc[ql][s*KC+i];
            while (q0<KC){ float v=sc[ql][os0*KC+q0]; if (v>m || (v==m && g0)) q0++; else break; }
            while (q1<KC){ float v=sc[ql][os1*KC+q1]; if (v>m || (v==m && g1)) q1++; else break; }
            while (q2<KC){ float v=sc[ql][os2*KC+q2]; if (v>m || (v==m && g2)) q2++; else break; }
            int rank = i + q0 + q1 + q2;
            if (rank < KC) ssel[ql][rank] = (s<<5) + i;
        }
    }
    __syncthreads();

    // fp64 rescore the 26 survivors (4 lanes/query, strided)
    const float* base = pts + (size_t)b * sB;
#pragma unroll 1
    for (int r=s; r<KC; r+=4){
        int code = ssel[ql][r];
        int cs = code>>5, ci = code&31;
        int cand = g_scrI[((size_t)qg*4 + cs)*KC + ci];
        double dot=0.0, qsq=0.0;
#pragma unroll 4
        for (int c=0;c<C;c++){
            double qv = (double)base[(size_t)cand*sN + (size_t)c*sC];
            double pv = (double)base[(size_t)row*sN + (size_t)c*sC];
            dot = fma(pv, qv, dot);
            qsq = fma(qv, qv, qsq);
        }
        dval[ql][r] = 2.0*dot - qsq;
        ssel[ql][r] = cand;
    }
    __syncthreads();

    // exact top-20 set by fp64 rank count
#pragma unroll 1
    for (int r=s; r<KC; r+=4){
        double di = dval[ql][r]; int ii = ssel[ql][r];
        int cnt = 0;
#pragma unroll 1
        for (int r2=0;r2<KC;r2++){
            double dk = dval[ql][r2]; int ik = ssel[ql][r2];
            bool gt = (dk > di) || (dk == di && ik < ii);
            cnt += gt ? 1 : 0;
        }
        if (cnt < KK) g_idx[(size_t)qg*KK + cnt] = ii;
    }
}

__device__ __forceinline__ float lrelu(float v){ return v>0.f ? v : 0.2f*v; }

// ---------------- point GEMM from raw x (B,3,N): 3 -> 64 ----------------
__global__ void point_gemm3_kernel(const float* __restrict__ x, const float* __restrict__ W1,
                                   int mode, int out_sel)
{
    __shared__ float w[64][3];
    int tid = threadIdx.x;
    if (tid < 192){
        int o = tid/3, c = tid - o*3;
        w[o][c] = mode ? (W1[o*6+3+c] - W1[o*6+c]) : W1[o*6+c];
    }
    __syncthreads();
    int i = blockIdx.x*64 + (tid>>2);
    int og = tid & 3;
    int b = i>>11, n = i & (NN-1);
    const float* xb = x + (size_t)b*3*NN;
    float x0=xb[n], x1v=xb[NN+n], x2v=xb[2*NN+n];
    float* outp = (out_sel ? g_Pc : g_Pa) + ((size_t)i<<6) + og*16;
#pragma unroll
    for (int oo=0;oo<16;oo+=4){
        int ob = og*16+oo;
        float4 v;
        v.x = x0*w[ob+0][0] + x1v*w[ob+0][1] + x2v*w[ob+0][2];
        v.y = x0*w[ob+1][0] + x1v*w[ob+1][1] + x2v*w[ob+1][2];
        v.z = x0*w[ob+2][0] + x1v*w[ob+2][1] + x2v*w[ob+2][2];
        v.w = x0*w[ob+3][0] + x1v*w[ob+3][1] + x2v*w[ob+3][2];
        *reinterpret_cast<float4*>(outp+oo) = v;
    }
}

#define MMA8x4(a0,a1,b) \
    acc[0][0]+=a0.x*b.x; acc[0][1]+=a0.x*b.y; acc[0][2]+=a0.x*b.z; acc[0][3]+=a0.x*b.w; \
    acc[1][0]+=a0.y*b.x; acc[1][1]+=a0.y*b.y; acc[1][2]+=a0.y*b.z; acc[1][3]+=a0.y*b.w; \
    acc[2][0]+=a0.z*b.x; acc[2][1]+=a0.z*b.y; acc[2][2]+=a0.z*b.z; acc[2][3]+=a0.z*b.w; \
    acc[3][0]+=a0.w*b.x; acc[3][1]+=a0.w*b.y; acc[3][2]+=a0.w*b.z; acc[3][3]+=a0.w*b.w; \
    acc[4][0]+=a1.x*b.x; acc[4][1]+=a1.x*b.y; acc[4][2]+=a1.x*b.z; acc[4][3]+=a1.x*b.w; \
    acc[5][0]+=a1.y*b.x; acc[5][1]+=a1.y*b.y; acc[5][2]+=a1.y*b.z; acc[5][3]+=a1.y*b.w; \
    acc[6][0]+=a1.z*b.x; acc[6][1]+=a1.z*b.y; acc[6][2]+=a1.z*b.z; acc[6][3]+=a1.z*b.w; \
    acc[7][0]+=a1.w*b.x; acc[7][1]+=a1.w*b.y; acc[7][2]+=a1.w*b.z; acc[7][3]+=a1.w*b.w;

#define STATS_EPILOGUE(accL, base_off, Cn) \
    { \
        float4 sv, qv_; \
        { float s0=0,s1=0,s2=0,s3=0,q0=0,q1=0,q2=0,q3=0; \
          _Pragma("unroll") \
          for (int j=0;j<8;j++){ \
              float v0=acc[j][0],v1=acc[j][1],v2=acc[j][2],v3=acc[j][3]; \
              s0+=v0;s1+=v1;s2+=v2;s3+=v3; q0+=v0*v0;q1+=v1*v1;q2+=v2*v2;q3+=v3*v3; } \
          sv=make_float4(s0,s1,s2,s3); qv_=make_float4(q0,q1,q2,q3); } \
        sps4[ty][tx]=sv; spq4[ty][tx]=qv_; \
        __syncthreads(); \
        if (tid < 64){ \
            const float* fs_=reinterpret_cast<const float*>(sps4); \
            const float* fq_=reinterpret_cast<const float*>(spq4); \
            double s=0.0,q=0.0; \
            _Pragma("unroll") \
            for (int j=0;j<16;j++){ s+=(double)fs_[j*64+tid]; q+=(double)fq_[j*64+tid]; } \
            double* accp = g_accR + (size_t)(blockIdx.x & (NREP-1))*12288 + (accL)*2048; \
            atomicAdd(&accp[(base_off) + tid],        s); \
            atomicAdd(&accp[(Cn) + (base_off) + tid], q); \
        } \
    }

// ---------------- gather GEMM (R13 shape): A=lrelu(BN(Pa[nbr]+Pc[cen])), fused stats + max/min ----------------
__global__ void conv_gather_gemm(int bn_layer, int stat_layer, const float* __restrict__ W, int tab)
{
    __shared__ __align__(16) float As[32][132];
    __shared__ __align__(16) float Ws[64][68];
    __shared__ __align__(16) float4 s_sc[16], s_sh[16];
    __shared__ __align__(16) float4 sps4[16][16], spq4[16][16];
    __shared__ int s_cen[128], s_nbr[128];
    int tid = threadIdx.x;
    int eb = blockIdx.x*128;
    if (tid < 16){
        s_sc[tid] = reinterpret_cast<const float4*>(g_scale + bn_layer*1024)[tid];
        s_sh[tid] = reinterpret_cast<const float4*>(g_shift + bn_layer*1024)[tid];
    }
    if (tid < 128){
        int e = eb+tid;
        int bn = e/KK;
        s_cen[tid]=bn;
        s_nbr[tid]=(bn & ~(NN-1)) + g_idx[e];
    }
    {
        const float4* w4 = reinterpret_cast<const float4*>(W);
#pragma unroll 2
        for (int i=tid;i<1024;i+=256){
            int o=i>>4, kq=i&15; int kk=kq<<2;
            float4 w = w4[i];
            Ws[kk][o]=w.x; Ws[kk+1][o]=w.y; Ws[kk+2][o]=w.z; Ws[kk+3][o]=w.w;
        }
    }
    int tx=tid&15, ty=tid>>4;
    float acc[8][4];
#pragma unroll
    for (int j=0;j<8;j++){
#pragma unroll
        for (int i=0;i<4;i++) acc[j][i]=0.f;
    }
    const float4* Pa4 = reinterpret_cast<const float4*>(g_Pa);
    const float4* Pc4 = reinterpret_cast<const float4*>(g_Pc);
#pragma unroll 1
    for (int chunk=0; chunk<2; chunk++){
        __syncthreads();
#pragma unroll 2
        for (int i=tid;i<1024;i+=256){
            int e=i>>3, kq=i&7;
            int kg=(chunk<<3)+kq;
            float4 a = Pa4[((size_t)s_nbr[e]<<4)+kg];
            float4 c = Pc4[((size_t)s_cen[e]<<4)+kg];
            float4 sc=s_sc[kg], sh=s_sh[kg];
            int kk=kq<<2;
            As[kk  ][e]=lrelu((a.x+c.x)*sc.x+sh.x);
            As[kk+1][e]=lrelu((a.y+c.y)*sc.y+sh.y);
            As[kk+2][e]=lrelu((a.z+c.z)*sc.z+sh.z);
            As[kk+3][e]=lrelu((a.w+c.w)*sc.w+sh.w);
        }
        __syncthreads();
        int kb = chunk<<5;
#pragma unroll 8
        for (int k=0;k<32;k++){
            float4 a0 = *reinterpret_cast<const float4*>(&As[k][ty<<3]);
            float4 a1 = *reinterpret_cast<const float4*>(&As[k][(ty<<3)+4]);
            float4 b  = *reinterpret_cast<const float4*>(&Ws[kb+k][tx<<2]);
            MMA8x4(a0,a1,b)
        }
    }
    __syncthreads();
    STATS_EPILOGUE(stat_layer, 0, 64)

    unsigned* encMax = reinterpret_cast<unsigned*>(g_tab) + (size_t)tab*2*PTCH;
    unsigned* encMin = encMax + PTCH;
    int c0 = eb/KK;
#pragma unroll 1
    for (int chunk=0; chunk<2; chunk++){
        __syncthreads();
        if ((tx>>3)==chunk){
            int cb = (tx&7)<<2;
#pragma unroll
            for (int j=0;j<8;j++){
#pragma unroll
                for (int i=0;i<4;i++) As[cb+i][(ty<<3)+j] = acc[j][i];
            }
        }
        __syncthreads();
        int ch = tid & 31, cslot = tid>>5;
        int ci = c0 + cslot;
        int lo = ci*KK - eb;     if (lo<0)  lo=0;
        int hi = ci*KK+KK - eb;  if (hi>128) hi=128;
        if (lo < hi && ci < NPTS){
            float m=-3.4e38f, mn=3.4e38f;
            for (int e=lo;e<hi;e++){
                float v = As[ch][e];
                m = fmaxf(m,v); mn = fminf(mn,v);
            }
            atomicMax(&encMax[(size_t)ci*64 + (chunk<<5) + ch], fenc(m));
            atomicMin(&encMin[(size_t)ci*64 + (chunk<<5) + ch], fenc(mn));
        }
    }
}

// ---------------- point GEMM (64ch): P = pts @ Wa^T (mode 0) or pts @ (Wb-Wa)^T (mode 1) ----------------
__global__ void point_gemm_kernel(int sel_pts, const float* __restrict__ W, int mode, int out_sel)
{
    const float* pts = sel_pts==1 ? g_x1 : g_x2;
    float* outp = out_sel==0 ? g_Pa : g_Pc;
    __shared__ __align__(16) float As[32][132];
    __shared__ __align__(16) float Ws[64][68];
    int tid = threadIdx.x;
    int pb = blockIdx.x*128;
    {
        const float4* w4 = reinterpret_cast<const float4*>(W);
#pragma unroll 2
        for (int i=tid;i<1024;i+=256){
            int o=i>>4, kq=i&15; int kk=kq<<2;
            float4 w;
            if (mode){
                float4 wb = w4[(o<<5) + 16 + kq];
                float4 wa = w4[(o<<5) + kq];
                w = make_float4(wb.x-wa.x, wb.y-wa.y, wb.z-wa.z, wb.w-wa.w);
            } else {
                w = w4[(o<<5) + kq];
            }
            Ws[kk][o]=w.x; Ws[kk+1][o]=w.y; Ws[kk+2][o]=w.z; Ws[kk+3][o]=w.w;
        }
    }
    int tx=tid&15, ty=tid>>4;
    float acc[8][4];
#pragma unroll
    for (int j=0;j<8;j++){
#pragma unroll
        for (int i=0;i<4;i++) acc[j][i]=0.f;
    }
    const float4* h4 = reinterpret_cast<const float4*>(pts + ((size_t)pb<<6));
#pragma unroll 1
    for (int chunk=0; chunk<2; chunk++){
        __syncthreads();
#pragma unroll 2
        for (int i=tid;i<1024;i+=256){
            int e=i>>3, kq=i&7;
            int kg=(chunk<<3)+kq;
            float4 v = h4[(e<<4)+kg];
            int kk=kq<<2;
            As[kk][e]=v.x; As[kk+1][e]=v.y; As[kk+2][e]=v.z; As[kk+3][e]=v.w;
        }
        __syncthreads();
        int kb = chunk<<5;
#pragma unroll 8
        for (int k=0;k<32;k++){
            float4 a0 = *reinterpret_cast<const float4*>(&As[k][ty<<3]);
            float4 a1 = *reinterpret_cast<const float4*>(&As[k][(ty<<3)+4]);
            float4 b  = *reinterpret_cast<const float4*>(&Ws[kb+k][tx<<2]);
            MMA8x4(a0,a1,b)
        }
    }
#pragma unroll
    for (int j=0;j<8;j++){
        float4 v = make_float4(acc[j][0],acc[j][1],acc[j][2],acc[j][3]);
        *reinterpret_cast<float4*>(&outp[((size_t)(pb+(ty<<3)+j)<<6)+(tx<<2)]) = v;
    }
}

// ---------------- center reduce: stats (+optional pre-BN max/min) from Pa/Pc ----------------
__global__ void center_reduce_kernel(int stat_layer, int write_pre)
{
    __shared__ int s_idx[64*KK];
    __shared__ float fs[64][68];
    __shared__ float fq[64][68];
    __shared__ float pfold[2][256];
    int tid = threadIdx.x;
    int nb = blockIdx.x*64;
    for (int i=tid;i<64*KK;i+=256) s_idx[i] = g_idx[(size_t)nb*KK + i];
    __syncthreads();
    int cen_l = tid>>2, cq = tid&3;
    int bn = nb + cen_l;
    int base = bn & ~(NN-1);
    const float4* Pa4 = reinterpret_cast<const float4*>(g_Pa);
    const float4* Pc4 = reinterpret_cast<const float4*>(g_Pc);
    float4 S1[4], S2[4], Mx[4], Mn[4];
#pragma unroll
    for (int i=0;i<4;i++){
        S1[i]=make_float4(0,0,0,0); S2[i]=make_float4(0,0,0,0);
        Mx[i]=make_float4(-3.4e38f,-3.4e38f,-3.4e38f,-3.4e38f);
        Mn[i]=make_float4( 3.4e38f, 3.4e38f, 3.4e38f, 3.4e38f);
    }
#pragma unroll 1
    for (int k=0;k<KK;k++){
        size_t idx = (size_t)(base + s_idx[cen_l*KK+k]);
        const float4* r = Pa4 + (idx<<4) + (cq<<2);
#pragma unroll
        for (int i=0;i<4;i++){
            float4 v = r[i];
            S1[i].x+=v.x; S1[i].y+=v.y; S1[i].z+=v.z; S1[i].w+=v.w;
            S2[i].x+=v.x*v.x; S2[i].y+=v.y*v.y; S2[i].z+=v.z*v.z; S2[i].w+=v.w*v.w;
            Mx[i].x=fmaxf(Mx[i].x,v.x); Mx[i].y=fmaxf(Mx[i].y,v.y);
            Mx[i].z=fmaxf(Mx[i].z,v.z); Mx[i].w=fmaxf(Mx[i].w,v.w);
            Mn[i].x=fminf(Mn[i].x,v.x); Mn[i].y=fminf(Mn[i].y,v.y);
            Mn[i].z=fminf(Mn[i].z,v.z); Mn[i].w=fminf(Mn[i].w,v.w);
        }
    }
    const float4* pr = Pc4 + ((size_t)bn<<4) + (cq<<2);
    float* preMax = g_tab + 4*PTCH;
    float* preMin = g_tab + 5*PTCH;
#pragma unroll
    for (int i=0;i<4;i++){
        float4 c = pr[i];
        float4 s4v, q4v;
        s4v.x = S1[i].x + 20.f*c.x;  q4v.x = S2[i].x + 2.f*c.x*S1[i].x + 20.f*c.x*c.x;
        s4v.y = S1[i].y + 20.f*c.y;  q4v.y = S2[i].y + 2.f*c.y*S1[i].y + 20.f*c.y*c.y;
        s4v.z = S1[i].z + 20.f*c.z;  q4v.z = S2[i].z + 2.f*c.z*S1[i].z + 20.f*c.z*c.z;
        s4v.w = S1[i].w + 20.f*c.w;  q4v.w = S2[i].w + 2.f*c.w*S1[i].w + 20.f*c.w*c.w;
        int cbase = (cq<<4) + (i<<2);
        fs[cen_l][cbase+0]=s4v.x; fs[cen_l][cbase+1]=s4v.y; fs[cen_l][cbase+2]=s4v.z; fs[cen_l][cbase+3]=s4v.w;
        fq[cen_l][cbase+0]=q4v.x; fq[cen_l][cbase+1]=q4v.y; fq[cen_l][cbase+2]=q4v.z; fq[cen_l][cbase+3]=q4v.w;
        if (write_pre){
            float4 mx = make_float4(Mx[i].x+c.x, Mx[i].y+c.y, Mx[i].z+c.z, Mx[i].w+c.w);
            float4 mn = make_float4(Mn[i].x+c.x, Mn[i].y+c.y, Mn[i].z+c.z, Mn[i].w+c.w);
            *reinterpret_cast<float4*>(preMax + ((size_t)bn<<6) + cbase) = mx;
            *reinterpret_cast<float4*>(preMin + ((size_t)bn<<6) + cbase) = mn;
        }
    }
    __syncthreads();
    {
        int ch = tid & 63, grp = tid>>6;
        float s=0.f,q=0.f;
#pragma unroll
        for (int i=0;i<16;i++){ s+=fs[grp*16+i][ch]; q+=fq[grp*16+i][ch]; }
        pfold[0][tid]=s; pfold[1][tid]=q;
    }
    __syncthreads();
    if (tid<64){
        double S = (double)pfold[0][tid]+pfold[0][64+tid]+pfold[0][128+tid]+pfold[0][192+tid];
        double Q = (double)pfold[1][tid]+pfold[1][64+tid]+pfold[1][128+tid]+pfold[1][192+tid];
        double* accp = g_accR + (size_t)(blockIdx.x & (NREP-1))*12288 + stat_layer*2048;
        atomicAdd(&accp[tid],    S);
        atomicAdd(&accp[64+tid], Q);
    }
}

// ---------------- BN-apply on encoded max/min tables -> x1/x2 ----------------
__global__ void maxpool_apply_enc(int layer, int tab, int out_sel)
{
    int i = blockIdx.x*256 + threadIdx.x;
    if (i < PTCH){
        int c = i & 63;
        float sc = g_scale[layer*1024+c], sh = g_shift[layer*1024+c];
        const unsigned* base = reinterpret_cast<const unsigned*>(g_tab) + (size_t)tab*2*PTCH;
        unsigned e = (sc >= 0.f) ? base[i] : base[PTCH + i];
        float v = fdec(e)*sc + sh;
        float* outp = out_sel==0 ? g_x1 : g_x2;
        outp[i] = v>0.f ? v : 0.2f*v;
    }
}

// ---------------- BN-apply on plain pre tables -> x3 (block 3) ----------------
__global__ void maxpool_apply_kernel(int layer)
{
    int i = blockIdx.x*256 + threadIdx.x;
    if (i < PTCH){
        int c = i & 63;
        float sc = g_scale[layer*1024+c], sh = g_shift[layer*1024+c];
        float pre = (sc >= 0.f) ? g_tab[4*PTCH + i] : g_tab[5*PTCH + i];
        float v = pre*sc + sh;
        g_x3[i] = v>0.f ? v : 0.2f*v;
    }
}

// ---------------- conv6 (R13 shape): cat[x1,x2,x3] (192) -> 1024, fused stats ----------------
__global__ void conv6_kernel(const float* __restrict__ W6)
{
    __shared__ __align__(16) float As[32][132];
    __shared__ __align__(16) float Ws[64][68];
    __shared__ __align__(16) float4 sps4[16][16], spq4[16][16];
    int tid=threadIdx.x;
    int rb = blockIdx.x*128;
    int ob = blockIdx.y*64;
    int tx=tid&15, ty=tid>>4;
    float acc[8][4];
#pragma unroll
    for (int j=0;j<8;j++){
#pragma unroll
        for (int i=0;i<4;i++) acc[j][i]=0.f;
    }
    const float4* w4 = reinterpret_cast<const float4*>(W6);
#pragma unroll 1
    for (int t=0;t<3;t++){
        const float* src = (t==0)? g_x1 : (t==1)? g_x2 : g_x3;
        const float4* s4 = reinterpret_cast<const float4*>(src + ((size_t)rb<<6));
        __syncthreads();
#pragma unroll 2
        for (int i=tid;i<1024;i+=256){
            int o=i>>4, kq=i&15; int kk=kq<<2;
            float4 w = w4[(size_t)(ob+o)*48 + (t<<4) + kq];
            Ws[kk][o]=w.x; Ws[kk+1][o]=w.y; Ws[kk+2][o]=w.z; Ws[kk+3][o]=w.w;
        }
#pragma unroll 1
        for (int chunk=0; chunk<2; chunk++){
            if (chunk) __syncthreads();
#pragma unroll 2
            for (int i=tid;i<1024;i+=256){
                int e=i>>3, kq=i&7;
                int kg=(chunk<<3)+kq;
                float4 v = s4[(e<<4)+kg];
                int kk=kq<<2;
                As[kk][e]=v.x; As[kk+1][e]=v.y; As[kk+2][e]=v.z; As[kk+3][e]=v.w;
            }
            __syncthreads();
            int kb = chunk<<5;
#pragma unroll 8
            for (int k=0;k<32;k++){
                float4 a0 = *reinterpret_cast<const float4*>(&As[k][ty<<3]);
                float4 a1 = *reinterpret_cast<const float4*>(&As[k][(ty<<3)+4]);
                float4 b  = *reinterpret_cast<const float4*>(&Ws[kb+k][tx<<2]);
                MMA8x4(a0,a1,b)
            }
        }
    }
#pragma unroll
    for (int j=0;j<8;j++){
        float4 v = make_float4(acc[j][0],acc[j][1],acc[j][2],acc[j][3]);
        *reinterpret_cast<float4*>(&g_ypre[(size_t)(rb+(ty<<3)+j)*1024 + ob + (tx<<2)]) = v;
    }
    __syncthreads();
    STATS_EPILOGUE(5, ob, 1024)
}

__global__ void finalize_kernel(int layer, const float* __restrict__ g,
                                const float* __restrict__ bparam, float inv, int C)
{
    int c = threadIdx.x + blockIdx.x*blockDim.x;
    if (c<C){
        double s=0.0, q=0.0;
#pragma unroll 4
        for (int r=0;r<NREP;r++){
            const double* acc = g_accR + (size_t)r*12288 + layer*2048;
            s += acc[c]; q += acc[C+c];
        }
        double mean = s*(double)inv;
        double var  = q*(double)inv - mean*mean;
        float is = rsqrtf((float)var + EPSV)*g[c];
        g_scale[layer*1024+c]=is;
        g_shift[layer*1024+c]=bparam[c]-(float)mean*is;
    }
}

// ---------------- BN+lrelu + transpose (b,n,o) -> (b,o,n) into d_out ----------------
__global__ void final_y_kernel(float* __restrict__ out)
{
    __shared__ float tile[32][33];
    int b = blockIdx.z;
    int n0 = blockIdx.x<<5, o0 = blockIdx.y<<5;
    int tx = threadIdx.x, ty = threadIdx.y;
    float sc = g_scale[5*1024+o0+tx], sh = g_shift[5*1024+o0+tx];
#pragma unroll
    for (int r=0;r<4;r++){
        int n = n0+ty+(r<<3);
        float v = g_ypre[(size_t)(b*NN+n)*1024 + o0+tx]*sc+sh;
        v = v>0.f ? v : 0.2f*v;
        tile[ty+(r<<3)][tx]=v;
    }
    __syncthreads();
#pragma unroll
    for (int r=0;r<4;r++){
        int o = o0+ty+(r<<3);
        out[(size_t)b*NN*1024 + (size_t)o*NN + n0+tx] = tile[tx][ty+(r<<3)];
    }
}

// ---------------- argmax / max over N per (b, channel) ----------------
__global__ void pool_kernel(float* __restrict__ out)
{
    int bo = blockIdx.x;
    const float* row = out + (size_t)bo*NN;
    int tid=threadIdx.x;
    float best=-3.4e38f; int bidx=0x7fffffff;
    for (int n=tid;n<NN;n+=256){
        float v=row[n];
        if (v>best){best=v;bidx=n;}
    }
    __shared__ float sv[256]; __shared__ int si[256];
    sv[tid]=best; si[tid]=bidx;
    __syncthreads();
    for (int s=128;s>0;s>>=1){
        if (tid<s){
            float v2=sv[tid+s]; int i2=si[tid+s];
            if (v2>sv[tid] || (v2==sv[tid] && i2<si[tid])){ sv[tid]=v2; si[tid]=i2; }
        }
        __syncthreads();
    }
    if (tid==0){
        out[(size_t)BB*1024*NN + bo]            = (float)si[0];
        out[(size_t)BB*1024*NN + BB*1024 + bo]  = sv[0];
    }
}

// ---------------- launch ----------------
extern "C" void kernel_launch(void* const* d_in, const int* in_sizes, int n_in,
                              void* d_out, int out_size)
{
    const float* x  = (const float*)d_in[0];
    const float* W1 = (const float*)d_in[1];
    const float* W2 = (const float*)d_in[2];
    const float* W3 = (const float*)d_in[3];
    const float* W4 = (const float*)d_in[4];
    const float* W5 = (const float*)d_in[5];
    const float* W6 = (const float*)d_in[6];
    const float* g1=(const float*)d_in[7];  const float* b1=(const float*)d_in[8];
    const float* g2=(const float*)d_in[9];  const float* b2=(const float*)d_in[10];
    const float* g3=(const float*)d_in[11]; const float* b3=(const float*)d_in[12];
    const float* g4=(const float*)d_in[13]; const float* b4=(const float*)d_in[14];
    const float* g5=(const float*)d_in[15]; const float* b5=(const float*)d_in[16];
    const float* g6=(const float*)d_in[17]; const float* b6=(const float*)d_in[18];
    float* out = (float*)d_out;

    const float invE = 1.0f/(float)NEg;
    const float invR = 1.0f/(float)(BB*NN);
    dim3 kp(NN/128, 4, BB);          // knn phase A grid

    zero_acc_kernel<<<2048,256>>>();                          // 0

    // block 1 (knn_part<3> at captured slot 3)
    sqx_kernel<<<NPTS/256,256>>>(x);                          // 1
    point_gemm3_kernel<<<NPTS/64,256>>>(x, W1, 0, 0);         // 2  Pa1
    knn_part<3><<<kp,128>>>(x, 0, 3*NN, 1, NN);               // 3  <- profiled
    knn_merge<3><<<NPTS/64,256>>>(x, 0, 3*NN, 1, NN);         // 4
    point_gemm3_kernel<<<NPTS/64,256>>>(x, W1, 1, 1);         // 5  Pc1
    center_reduce_kernel<<<NPTS/64,256>>>(0, 0);              //    stats L0
    finalize_kernel<<<1,64>>>(0, g1, b1, invE, 64);
    conv_gather_gemm<<<NEg/128,256>>>(0, 1, W2, 0);           // stats L1 + enc max/min tab0
    finalize_kernel<<<1,64>>>(1, g2, b2, invE, 64);
    maxpool_apply_enc<<<(PTCH+255)/256,256>>>(1, 0, 0);       // -> x1

    // block 2
    sq64_kernel<<<NPTS/128,128>>>(1);
    knn_part<64><<<kp,128>>>(nullptr, 1, NN*64, 64, 1);
    knn_merge<64><<<NPTS/64,256>>>(nullptr, 1, NN*64, 64, 1);
    point_gemm_kernel<<<NPTS/128,256>>>(1, W3, 0, 0);
    point_gemm_kernel<<<NPTS/128,256>>>(1, W3, 1, 1);
    center_reduce_kernel<<<NPTS/64,256>>>(2, 0);              // stats L2
    finalize_kernel<<<1,64>>>(2, g3, b3, invE, 64);
    conv_gather_gemm<<<NEg/128,256>>>(2, 3, W4, 1);           // stats L3 + enc max/min tab1
    finalize_kernel<<<1,64>>>(3, g4, b4, invE, 64);
    maxpool_apply_enc<<<(PTCH+255)/256,256>>>(3, 1, 1);       // -> x2

    // block 3
    sq64_kernel<<<NPTS/128,128>>>(2);
    knn_part<64><<<kp,128>>>(nullptr, 2, NN*64, 64, 1);
    knn_merge<64><<<NPTS/64,256>>>(nullptr, 2, NN*64, 64, 1);
    point_gemm_kernel<<<NPTS/128,256>>>(2, W5, 0, 0);
    point_gemm_kernel<<<NPTS/128,256>>>(2, W5, 1, 1);
    center_reduce_kernel<<<NPTS/64,256>>>(4, 1);              // stats L4 + plain pre max/min
    finalize_kernel<<<1,64>>>(4, g5, b5, invE, 64);
    maxpool_apply_kernel<<<(PTCH+255)/256,256>>>(4);          // -> x3

    // head
    conv6_kernel<<<dim3(NPTS/128,16),256>>>(W6);              // -> ypre, stats L5
    finalize_kernel<<<4,256>>>(5, g6, b6, invR, 1024);
    final_y_kernel<<<dim3(NN/32, 1024/32, BB), dim3(32,8)>>>(out);
    pool_kernel<<<BB*1024,256>>>(out);
}

// round 16
// speedup vs baseline: 1.2215x; 1.2215x over previous
#include <cuda_runtime.h>

#define BB 16
#define NN 2048
#define KK 20
#define KC 26               // phase-A candidate count per subset (margin 6)
#define NEg (BB*NN*KK)      // 655360 edges
#define EPSV 1e-5f
#define NREP 32             // stats accumulator replication factor
#define NPTS (BB*NN)        // 32768 points
#define PTCH (NPTS*64)      // 2097152 entries per table

// ---------------- scratch (static device allocations) ----------------
__device__ float g_tab[12582912];         // enc max/min tables (4 x 2M) + plain pre tables (2 x 2M)
__device__ int   g_idx[NEg];
__device__ unsigned g_scrK[NPTS*4*KC];    // knn phase-A packed keys (sorted desc per subset)
__device__ float g_x1[PTCH];
__device__ float g_x2[PTCH];
__device__ float g_x3[PTCH];
__device__ float g_Pa[PTCH];
__device__ float g_Pc[PTCH];
__device__ float g_sq[NPTS];
__device__ float g_ypre[33554432];        // B*N*1024
__device__ double g_accR[NREP*6*2048];    // replicated per-layer sum/sumsq
__device__ float g_scale[6*1024];
__device__ float g_shift[6*1024];

__device__ __forceinline__ unsigned fenc(float f){
    unsigned b = __float_as_uint(f);
    return (b>>31) ? ~b : (b | 0x80000000u);
}
__device__ __forceinline__ float fdec(unsigned e){
    unsigned b = (e>>31) ? (e ^ 0x80000000u) : ~e;
    return __uint_as_float(b);
}

__global__ void zero_acc_kernel() {
    int i = blockIdx.x*256 + threadIdx.x;
    if (i < NREP*6*2048) g_accR[i] = 0.0;
    unsigned* t = reinterpret_cast<unsigned*>(g_tab);
    for (int j = i; j < 4*PTCH; j += gridDim.x*256)
        t[j] = ((j>>21)&1) ? 0xFFFFFFFFu : 0u;
}

// squared norms from raw x (B,3,N)
__global__ void sqx_kernel(const float* __restrict__ x){
    int i = blockIdx.x*256 + threadIdx.x;
    if (i < NPTS){
        int b = i >> 11, n = i & (NN-1);
        const float* xb = x + (size_t)b*3*NN;
        float a=xb[n], c=xb[NN+n], d=xb[2*NN+n];
        g_sq[i] = a*a + c*c + d*d;
    }
}

// squared norms from 64-channel point features
__global__ void sq64_kernel(int sel){
    const float* pts = (sel==1) ? g_x1 : g_x2;
    int i = blockIdx.x*128 + threadIdx.x;
    if (i < NPTS){
        const float4* p = reinterpret_cast<const float4*>(pts + ((size_t)i<<6));
        float s = 0.f;
#pragma unroll
        for (int q=0;q<16;q++){
            float4 v = p[q];
            s += v.x*v.x + v.y*v.y + v.z*v.z + v.w*v.w;
        }
        g_sq[i] = s;
    }
}

// ---------------- KNN phase A: 4-way split, packed-key top-26 (bubble-pass insertion) ----------------
template<int C>
__global__ void knn_part(const float* __restrict__ ext, int sel, int sB, int sN, int sC)
{
    const float* pts = (sel==0) ? ext : (sel==1 ? g_x1 : g_x2);
    __shared__ __align__(16) float tile[128][(C==3)?4:68];
    __shared__ float sqs[128];
    int b = blockIdx.z;
    int s = blockIdx.y;
    int row = blockIdx.x*128 + threadIdx.x;
    const float* base = pts + (size_t)b * sB;
    const float* sqb  = g_sq + (size_t)b * NN;

    float p[C];
#pragma unroll
    for (int c=0;c<C;c++) p[c] = base[(size_t)row*sN + (size_t)c*sC];

    unsigned bd[KC];
#pragma unroll
    for (int i=0;i<KC;i++) bd[i]=0u;
    unsigned worst = 0u;

    int t0 = s*512;
    for (int t=t0; t<t0+512; t+=128) {
        __syncthreads();
        if (C==3) {
            for (int i=threadIdx.x;i<128*3;i+=128){
                int c=i>>7, col=i&127;
                tile[col][c] = base[(size_t)(t+col)*sN + (size_t)c*sC];
            }
        } else {
            const float4* b4 = reinterpret_cast<const float4*>(base);
            for (int i=threadIdx.x;i<128*(C/4);i+=128){
                int col=i>>4, cq=i&15;
                *reinterpret_cast<float4*>(&tile[col][cq<<2]) =
                    b4[((size_t)(t+col)<<4)+cq];
            }
        }
        sqs[threadIdx.x] = sqb[t+threadIdx.x];
        __syncthreads();
#pragma unroll 1
        for (int j=0;j<128;j++) {
            float d;
            if (C==3) {
                d = 2.f*(p[0]*tile[j][0]+p[1]*tile[j][1]+p[2]*tile[j][2]) - sqs[j];
            } else {
                float d0=0.f,d1=0.f,d2=0.f,d3=0.f;
#pragma unroll
                for (int cq=0;cq<C/4;cq++){
                    float4 tv = *reinterpret_cast<const float4*>(&tile[j][cq*4]);
                    d0 += p[cq*4+0]*tv.x; d1 += p[cq*4+1]*tv.y;
                    d2 += p[cq*4+2]*tv.z; d3 += p[cq*4+3]*tv.w;
                }
                d = 2.f*((d0+d1)+(d2+d3)) - sqs[j];
            }
            unsigned key = (fenc(d) & 0xFFFFF800u) | (unsigned)(t + j);
            if (key > worst) {
                unsigned tmp = key;
#pragma unroll
                for (int ss=0; ss<KC; ss++){
                    unsigned hi = bd[ss] > tmp ? bd[ss] : tmp;
                    unsigned lo = bd[ss] > tmp ? tmp : bd[ss];
                    bd[ss] = hi; tmp = lo;
                }
                worst = bd[KC-1];
            }
        }
    }
    unsigned* oK = g_scrK + ((size_t)(b*NN+row)*4 + s)*KC;
#pragma unroll
    for (int i=0;i<KC;i++) oK[i]=bd[i];
}

// ---------------- KNN merge: rank union of 4 sorted key lists, fp64 rerank -> top-20 set ----------------
template<int C>
__global__ void __launch_bounds__(256) knn_merge(const float* __restrict__ ext,
                                                 int sel, int sB, int sN, int sC)
{
    const float* pts = (sel==0) ? ext : (sel==1 ? g_x1 : g_x2);
    __shared__ unsigned sc[64][104];
    __shared__ unsigned ssel[64][26];
    __shared__ double dval[64][26];
    int tid = threadIdx.x;
    int s  = tid & 3;
    int ql = tid >> 2;
    int qg = blockIdx.x*64 + ql;
    int b  = qg >> 11;
    int row = qg & (NN-1);

    {
        const unsigned* iK = g_scrK + ((size_t)qg*4 + s)*KC;
#pragma unroll
        for (int i=0;i<KC;i++) sc[ql][s*KC+i] = iK[i];
    }
    __syncthreads();

    // rank each own item within the 104-union (keys unique: strict compare)
    {
        int os0=(s+1)&3, os1=(s+2)&3, os2=(s+3)&3;
        int q0=0,q1=0,q2=0;
#pragma unroll 1
        for (int i=0;i<KC;i++){
            unsigned m = sc[ql][s*KC+i];
            while (q0<KC && sc[ql][os0*KC+q0] > m) q0++;
            while (q1<KC && sc[ql][os1*KC+q1] > m) q1++;
            while (q2<KC && sc[ql][os2*KC+q2] > m) q2++;
            int rank = i + q0 + q1 + q2;
            if (rank < KC) ssel[ql][rank] = m;
        }
    }
    __syncthreads();

    // fp64 rescore the 26 survivors (4 lanes/query, strided)
    const float* base = pts + (size_t)b * sB;
#pragma unroll 1
    for (int r=s; r<KC; r+=4){
        int cand = (int)(ssel[ql][r] & 2047u);
        double dot=0.0, qsq=0.0;
#pragma unroll 4
        for (int c=0;c<C;c++){
            double qv = (double)base[(size_t)cand*sN + (size_t)c*sC];
            double pv = (double)base[(size_t)row*sN + (size_t)c*sC];
            dot = fma(pv, qv, dot);
            qsq = fma(qv, qv, qsq);
        }
        dval[ql][r] = 2.0*dot - qsq;
        ssel[ql][r] = (unsigned)cand;
    }
    __syncthreads();

    // exact top-20 set by fp64 rank count
#pragma unroll 1
    for (int r=s; r<KC; r+=4){
        double di = dval[ql][r]; int ii = (int)ssel[ql][r];
        int cnt = 0;
#pragma unroll 1
        for (int r2=0;r2<KC;r2++){
            double dk = dval[ql][r2]; int ik = (int)ssel[ql][r2];
            bool gt = (dk > di) || (dk == di && ik < ii);
            cnt += gt ? 1 : 0;
        }
        if (cnt < KK) g_idx[(size_t)qg*KK + cnt] = ii;
    }
}

__device__ __forceinline__ float lrelu(float v){ return v>0.f ? v : 0.2f*v; }

// ---------------- point GEMM from raw x (B,3,N): 3 -> 64 ----------------
__global__ void point_gemm3_kernel(const float* __restrict__ x, const float* __restrict__ W1,
                                   int mode, int out_sel)
{
    __shared__ float w[64][3];
    int tid = threadIdx.x;
    if (tid < 192){
        int o = tid/3, c = tid - o*3;
        w[o][c] = mode ? (W1[o*6+3+c] - W1[o*6+c]) : W1[o*6+c];
    }
    __syncthreads();
    int i = blockIdx.x*64 + (tid>>2);
    int og = tid & 3;
    int b = i>>11, n = i & (NN-1);
    const float* xb = x + (size_t)b*3*NN;
    float x0=xb[n], x1v=xb[NN+n], x2v=xb[2*NN+n];
    float* outp = (out_sel ? g_Pc : g_Pa) + ((size_t)i<<6) + og*16;
#pragma unroll
    for (int oo=0;oo<16;oo+=4){
        int ob = og*16+oo;
        float4 v;
        v.x = x0*w[ob+0][0] + x1v*w[ob+0][1] + x2v*w[ob+0][2];
        v.y = x0*w[ob+1][0] + x1v*w[ob+1][1] + x2v*w[ob+1][2];
        v.z = x0*w[ob+2][0] + x1v*w[ob+2][1] + x2v*w[ob+2][2];
        v.w = x0*w[ob+3][0] + x1v*w[ob+3][1] + x2v*w[ob+3][2];
        *reinterpret_cast<float4*>(outp+oo) = v;
    }
}

#define MMA8x4(a0,a1,b) \
    acc[0][0]+=a0.x*b.x; acc[0][1]+=a0.x*b.y; acc[0][2]+=a0.x*b.z; acc[0][3]+=a0.x*b.w; \
    acc[1][0]+=a0.y*b.x; acc[1][1]+=a0.y*b.y; acc[1][2]+=a0.y*b.z; acc[1][3]+=a0.y*b.w; \
    acc[2][0]+=a0.z*b.x; acc[2][1]+=a0.z*b.y; acc[2][2]+=a0.z*b.z; acc[2][3]+=a0.z*b.w; \
    acc[3][0]+=a0.w*b.x; acc[3][1]+=a0.w*b.y; acc[3][2]+=a0.w*b.z; acc[3][3]+=a0.w*b.w; \
    acc[4][0]+=a1.x*b.x; acc[4][1]+=a1.x*b.y; acc[4][2]+=a1.x*b.z; acc[4][3]+=a1.x*b.w; \
    acc[5][0]+=a1.y*b.x; acc[5][1]+=a1.y*b.y; acc[5][2]+=a1.y*b.z; acc[5][3]+=a1.y*b.w; \
    acc[6][0]+=a1.z*b.x; acc[6][1]+=a1.z*b.y; acc[6][2]+=a1.z*b.z; acc[6][3]+=a1.z*b.w; \
    acc[7][0]+=a1.w*b.x; acc[7][1]+=a1.w*b.y; acc[7][2]+=a1.w*b.z; acc[7][3]+=a1.w*b.w;

#define STATS_EPILOGUE(accL, base_off, Cn) \
    { \
        float4 sv, qv_; \
        { float s0=0,s1=0,s2=0,s3=0,q0=0,q1=0,q2=0,q3=0; \
          _Pragma("unroll") \
          for (int j=0;j<8;j++){ \
              float v0=acc[j][0],v1=acc[j][1],v2=acc[j][2],v3=acc[j][3]; \
              s0+=v0;s1+=v1;s2+=v2;s3+=v3; q0+=v0*v0;q1+=v1*v1;q2+=v2*v2;q3+=v3*v3; } \
          sv=make_float4(s0,s1,s2,s3); qv_=make_float4(q0,q1,q2,q3); } \
        sps4[ty][tx]=sv; spq4[ty][tx]=qv_; \
        __syncthreads(); \
        if (tid < 64){ \
            const float* fs_=reinterpret_cast<const float*>(sps4); \
            const float* fq_=reinterpret_cast<const float*>(spq4); \
            double s=0.0,q=0.0; \
            _Pragma("unroll") \
            for (int j=0;j<16;j++){ s+=(double)fs_[j*64+tid]; q+=(double)fq_[j*64+tid]; } \
            double* accp = g_accR + (size_t)(blockIdx.x & (NREP-1))*12288 + (accL)*2048; \
            atomicAdd(&accp[(base_off) + tid],        s); \
            atomicAdd(&accp[(Cn) + (base_off) + tid], q); \
        } \
    }

// ---------------- gather GEMM: A=lrelu(BN(Pa[nbr]+Pc[cen])), fused stats + per-center max/min ----------------
__global__ void conv_gather_gemm(int bn_layer, int stat_layer, const float* __restrict__ W, int tab)
{
    __shared__ __align__(16) float As[32][132];
    __shared__ __align__(16) float Ws[64][68];
    __shared__ __align__(16) float4 s_sc[16], s_sh[16];
    __shared__ __align__(16) float4 sps4[16][16], spq4[16][16];
    __shared__ int s_cen[128], s_nbr[128];
    int tid = threadIdx.x;
    int eb = blockIdx.x*128;
    if (tid < 16){
        s_sc[tid] = reinterpret_cast<const float4*>(g_scale + bn_layer*1024)[tid];
        s_sh[tid] = reinterpret_cast<const float4*>(g_shift + bn_layer*1024)[tid];
    }
    if (tid < 128){
        int e = eb+tid;
        int bn = e/KK;
        s_cen[tid]=bn;
        s_nbr[tid]=(bn & ~(NN-1)) + g_idx[e];
    }
    {
        const float4* w4 = reinterpret_cast<const float4*>(W);
#pragma unroll 2
        for (int i=tid;i<1024;i+=256){
            int o=i>>4, kq=i&15; int kk=kq<<2;
            float4 w = w4[i];
            Ws[kk][o]=w.x; Ws[kk+1][o]=w.y; Ws[kk+2][o]=w.z; Ws[kk+3][o]=w.w;
        }
    }
    int tx=tid&15, ty=tid>>4;
    float acc[8][4];
#pragma unroll
    for (int j=0;j<8;j++){
#pragma unroll
        for (int i=0;i<4;i++) acc[j][i]=0.f;
    }
    const float4* Pa4 = reinterpret_cast<const float4*>(g_Pa);
    const float4* Pc4 = reinterpret_cast<const float4*>(g_Pc);
#pragma unroll 1
    for (int chunk=0; chunk<2; chunk++){
        __syncthreads();
#pragma unroll 2
        for (int i=tid;i<1024;i+=256){
            int e=i>>3, kq=i&7;
            int kg=(chunk<<3)+kq;
            float4 a = Pa4[((size_t)s_nbr[e]<<4)+kg];
            float4 c = Pc4[((size_t)s_cen[e]<<4)+kg];
            float4 sc=s_sc[kg], sh=s_sh[kg];
            int kk=kq<<2;
            As[kk  ][e]=lrelu((a.x+c.x)*sc.x+sh.x);
            As[kk+1][e]=lrelu((a.y+c.y)*sc.y+sh.y);
            As[kk+2][e]=lrelu((a.z+c.z)*sc.z+sh.z);
            As[kk+3][e]=lrelu((a.w+c.w)*sc.w+sh.w);
        }
        __syncthreads();
        int kb = chunk<<5;
#pragma unroll 8
        for (int k=0;k<32;k++){
            float4 a0 = *reinterpret_cast<const float4*>(&As[k][ty<<3]);
            float4 a1 = *reinterpret_cast<const float4*>(&As[k][(ty<<3)+4]);
            float4 b  = *reinterpret_cast<const float4*>(&Ws[kb+k][tx<<2]);
            MMA8x4(a0,a1,b)
        }
    }
    __syncthreads();
    STATS_EPILOGUE(stat_layer, 0, 64)

    unsigned* encMax = reinterpret_cast<unsigned*>(g_tab) + (size_t)tab*2*PTCH;
    unsigned* encMin = encMax + PTCH;
    int c0 = eb/KK;
#pragma unroll 1
    for (int chunk=0; chunk<2; chunk++){
        __syncthreads();
        if ((tx>>3)==chunk){
            int cb = (tx&7)<<2;
#pragma unroll
            for (int j=0;j<8;j++){
#pragma unroll
                for (int i=0;i<4;i++) As[cb+i][(ty<<3)+j] = acc[j][i];
            }
        }
        __syncthreads();
        int ch = tid & 31, cslot = tid>>5;
        int ci = c0 + cslot;
        int lo = ci*KK - eb;     if (lo<0)  lo=0;
        int hi = ci*KK+KK - eb;  if (hi>128) hi=128;
        if (lo < hi && ci < NPTS){
            float m=-3.4e38f, mn=3.4e38f;
            for (int e=lo;e<hi;e++){
                float v = As[ch][e];
                m = fmaxf(m,v); mn = fminf(mn,v);
            }
            atomicMax(&encMax[(size_t)ci*64 + (chunk<<5) + ch], fenc(m));
            atomicMin(&encMin[(size_t)ci*64 + (chunk<<5) + ch], fenc(mn));
        }
    }
}

// ---------------- point GEMM (64ch): P = pts @ Wa^T (mode 0) or pts @ (Wb-Wa)^T (mode 1) ----------------
__global__ void point_gemm_kernel(int sel_pts, const float* __restrict__ W, int mode, int out_sel)
{
    const float* pts = sel_pts==1 ? g_x1 : g_x2;
    float* outp = out_sel==0 ? g_Pa : g_Pc;
    __shared__ __align__(16) float As[32][132];
    __shared__ __align__(16) float Ws[64][68];
    int tid = threadIdx.x;
    int pb = blockIdx.x*128;
    {
        const float4* w4 = reinterpret_cast<const float4*>(W);
#pragma unroll 2
        for (int i=tid;i<1024;i+=256){
            int o=i>>4, kq=i&15; int kk=kq<<2;
            float4 w;
            if (mode){
                float4 wb = w4[(o<<5) + 16 + kq];
                float4 wa = w4[(o<<5) + kq];
                w = make_float4(wb.x-wa.x, wb.y-wa.y, wb.z-wa.z, wb.w-wa.w);
            } else {
                w = w4[(o<<5) + kq];
            }
            Ws[kk][o]=w.x; Ws[kk+1][o]=w.y; Ws[kk+2][o]=w.z; Ws[kk+3][o]=w.w;
        }
    }
    int tx=tid&15, ty=tid>>4;
    float acc[8][4];
#pragma unroll
    for (int j=0;j<8;j++){
#pragma unroll
        for (int i=0;i<4;i++) acc[j][i]=0.f;
    }
    const float4* h4 = reinterpret_cast<const float4*>(pts + ((size_t)pb<<6));
#pragma unroll 1
    for (int chunk=0; chunk<2; chunk++){
        __syncthreads();
#pragma unroll 2
        for (int i=tid;i<1024;i+=256){
            int e=i>>3, kq=i&7;
            int kg=(chunk<<3)+kq;
            float4 v = h4[(e<<4)+kg];
            int kk=kq<<2;
            As[kk][e]=v.x; As[kk+1][e]=v.y; As[kk+2][e]=v.z; As[kk+3][e]=v.w;
        }
        __syncthreads();
        int kb = chunk<<5;
#pragma unroll 8
        for (int k=0;k<32;k++){
            float4 a0 = *reinterpret_cast<const float4*>(&As[k][ty<<3]);
            float4 a1 = *reinterpret_cast<const float4*>(&As[k][(ty<<3)+4]);
            float4 b  = *reinterpret_cast<const float4*>(&Ws[kb+k][tx<<2]);
            MMA8x4(a0,a1,b)
        }
    }
#pragma unroll
    for (int j=0;j<8;j++){
        float4 v = make_float4(acc[j][0],acc[j][1],acc[j][2],acc[j][3]);
        *reinterpret_cast<float4*>(&outp[((size_t)(pb+(ty<<3)+j)<<6)+(tx<<2)]) = v;
    }
}

// ---------------- center reduce: stats (+optional pre-BN max/min) from Pa/Pc ----------------
__global__ void center_reduce_kernel(int stat_layer, int write_pre)
{
    __shared__ int s_idx[64*KK];
    __shared__ float fs[64][68];
    __shared__ float fq[64][68];
    __shared__ float pfold[2][256];
    int tid = threadIdx.x;
    int nb = blockIdx.x*64;
    for (int i=tid;i<64*KK;i+=256) s_idx[i] = g_idx[(size_t)nb*KK + i];
    __syncthreads();
    int cen_l = tid>>2, cq = tid&3;
    int bn = nb + cen_l;
    int base = bn & ~(NN-1);
    const float4* Pa4 = reinterpret_cast<const float4*>(g_Pa);
    const float4* Pc4 = reinterpret_cast<const float4*>(g_Pc);
    float4 S1[4], S2[4], Mx[4], Mn[4];
#pragma unroll
    for (int i=0;i<4;i++){
        S1[i]=make_float4(0,0,0,0); S2[i]=make_float4(0,0,0,0);
        Mx[i]=make_float4(-3.4e38f,-3.4e38f,-3.4e38f,-3.4e38f);
        Mn[i]=make_float4( 3.4e38f, 3.4e38f, 3.4e38f, 3.4e38f);
    }
#pragma unroll 1
    for (int k=0;k<KK;k++){
        size_t idx = (size_t)(base + s_idx[cen_l*KK+k]);
        const float4* r = Pa4 + (idx<<4) + (cq<<2);
#pragma unroll
        for (int i=0;i<4;i++){
            float4 v = r[i];
            S1[i].x+=v.x; S1[i].y+=v.y; S1[i].z+=v.z; S1[i].w+=v.w;
            S2[i].x+=v.x*v.x; S2[i].y+=v.y*v.y; S2[i].z+=v.z*v.z; S2[i].w+=v.w*v.w;
            Mx[i].x=fmaxf(Mx[i].x,v.x); Mx[i].y=fmaxf(Mx[i].y,v.y);
            Mx[i].z=fmaxf(Mx[i].z,v.z); Mx[i].w=fmaxf(Mx[i].w,v.w);
            Mn[i].x=fminf(Mn[i].x,v.x); Mn[i].y=fminf(Mn[i].y,v.y);
            Mn[i].z=fminf(Mn[i].z,v.z); Mn[i].w=fminf(Mn[i].w,v.w);
        }
    }
    const float4* pr = Pc4 + ((size_t)bn<<4) + (cq<<2);
    float* preMax = g_tab + 4*PTCH;
    float* preMin = g_tab + 5*PTCH;
#pragma unroll
    for (int i=0;i<4;i++){
        float4 c = pr[i];
        float4 s4v, q4v;
        s4v.x = S1[i].x + 20.f*c.x;  q4v.x = S2[i].x + 2.f*c.x*S1[i].x + 20.f*c.x*c.x;
        s4v.y = S1[i].y + 20.f*c.y;  q4v.y = S2[i].y + 2.f*c.y*S1[i].y + 20.f*c.y*c.y;
        s4v.z = S1[i].z + 20.f*c.z;  q4v.z = S2[i].z + 2.f*c.z*S1[i].z + 20.f*c.z*c.z;
        s4v.w = S1[i].w + 20.f*c.w;  q4v.w = S2[i].w + 2.f*c.w*S1[i].w + 20.f*c.w*c.w;
        int cbase = (cq<<4) + (i<<2);
        fs[cen_l][cbase+0]=s4v.x; fs[cen_l][cbase+1]=s4v.y; fs[cen_l][cbase+2]=s4v.z; fs[cen_l][cbase+3]=s4v.w;
        fq[cen_l][cbase+0]=q4v.x; fq[cen_l][cbase+1]=q4v.y; fq[cen_l][cbase+2]=q4v.z; fq[cen_l][cbase+3]=q4v.w;
        if (write_pre){
            float4 mx = make_float4(Mx[i].x+c.x, Mx[i].y+c.y, Mx[i].z+c.z, Mx[i].w+c.w);
            float4 mn = make_float4(Mn[i].x+c.x, Mn[i].y+c.y, Mn[i].z+c.z, Mn[i].w+c.w);
            *reinterpret_cast<float4*>(preMax + ((size_t)bn<<6) + cbase) = mx;
            *reinterpret_cast<float4*>(preMin + ((size_t)bn<<6) + cbase) = mn;
        }
    }
    __syncthreads();
    {
        int ch = tid & 63, grp = tid>>6;
        float s=0.f,q=0.f;
#pragma unroll
        for (int i=0;i<16;i++){ s+=fs[grp*16+i][ch]; q+=fq[grp*16+i][ch]; }
        pfold[0][tid]=s; pfold[1][tid]=q;
    }
    __syncthreads();
    if (tid<64){
        double S = (double)pfold[0][tid]+pfold[0][64+tid]+pfold[0][128+tid]+pfold[0][192+tid];
        double Q = (double)pfold[1][tid]+pfold[1][64+tid]+pfold[1][128+tid]+pfold[1][192+tid];
        double* accp = g_accR + (size_t)(blockIdx.x & (NREP-1))*12288 + stat_layer*2048;
        atomicAdd(&accp[tid],    S);
        atomicAdd(&accp[64+tid], Q);
    }
}

// ---------------- BN-apply on encoded max/min tables -> x1/x2 ----------------
__global__ void maxpool_apply_enc(int layer, int tab, int out_sel)
{
    int i = blockIdx.x*256 + threadIdx.x;
    if (i < PTCH){
        int c = i & 63;
        float sc = g_scale[layer*1024+c], sh = g_shift[layer*1024+c];
        const unsigned* base = reinterpret_cast<const unsigned*>(g_tab) + (size_t)tab*2*PTCH;
        unsigned e = (sc >= 0.f) ? base[i] : base[PTCH + i];
        float v = fdec(e)*sc + sh;
        float* outp = out_sel==0 ? g_x1 : g_x2;
        outp[i] = v>0.f ? v : 0.2f*v;
    }
}

// ---------------- BN-apply on plain pre tables -> x3 (block 3) ----------------
__global__ void maxpool_apply_kernel(int layer)
{
    int i = blockIdx.x*256 + threadIdx.x;
    if (i < PTCH){
        int c = i & 63;
        float sc = g_scale[layer*1024+c], sh = g_shift[layer*1024+c];
        float pre = (sc >= 0.f) ? g_tab[4*PTCH + i] : g_tab[5*PTCH + i];
        float v = pre*sc + sh;
        g_x3[i] = v>0.f ? v : 0.2f*v;
    }
}

// ---------------- conv6: cat[x1,x2,x3] (192) -> 1024, fused stats ----------------
__global__ void conv6_kernel(const float* __restrict__ W6)
{
    __shared__ __align__(16) float As[32][132];
    __shared__ __align__(16) float Ws[64][68];
    __shared__ __align__(16) float4 sps4[16][16], spq4[16][16];
    int tid=threadIdx.x;
    int rb = blockIdx.x*128;
    int ob = blockIdx.y*64;
    int tx=tid&15, ty=tid>>4;
    float acc[8][4];
#pragma unroll
    for (int j=0;j<8;j++){
#pragma unroll
        for (int i=0;i<4;i++) acc[j][i]=0.f;
    }
    const float4* w4 = reinterpret_cast<const float4*>(W6);
#pragma unroll 1
    for (int t=0;t<3;t++){
        const float* src = (t==0)? g_x1 : (t==1)? g_x2 : g_x3;
        const float4* s4 = reinterpret_cast<const float4*>(src + ((size_t)rb<<6));
        __syncthreads();
#pragma unroll 2
        for (int i=tid;i<1024;i+=256){
            int o=i>>4, kq=i&15; int kk=kq<<2;
            float4 w = w4[(size_t)(ob+o)*48 + (t<<4) + kq];
            Ws[kk][o]=w.x; Ws[kk+1][o]=w.y; Ws[kk+2][o]=w.z; Ws[kk+3][o]=w.w;
        }
#pragma unroll 1
        for (int chunk=0; chunk<2; chunk++){
            if (chunk) __syncthreads();
#pragma unroll 2
            for (int i=tid;i<1024;i+=256){
                int e=i>>3, kq=i&7;
                int kg=(chunk<<3)+kq;
                float4 v = s4[(e<<4)+kg];
                int kk=kq<<2;
                As[kk][e]=v.x; As[kk+1][e]=v.y; As[kk+2][e]=v.z; As[kk+3][e]=v.w;
            }
            __syncthreads();
            int kb = chunk<<5;
#pragma unroll 8
            for (int k=0;k<32;k++){
                float4 a0 = *reinterpret_cast<const float4*>(&As[k][ty<<3]);
                float4 a1 = *reinterpret_cast<const float4*>(&As[k][(ty<<3)+4]);
                float4 b  = *reinterpret_cast<const float4*>(&Ws[kb+k][tx<<2]);
                MMA8x4(a0,a1,b)
            }
        }
    }
#pragma unroll
    for (int j=0;j<8;j++){
        float4 v = make_float4(acc[j][0],acc[j][1],acc[j][2],acc[j][3]);
        *reinterpret_cast<float4*>(&g_ypre[(size_t)(rb+(ty<<3)+j)*1024 + ob + (tx<<2)]) = v;
    }
    __syncthreads();
    STATS_EPILOGUE(5, ob, 1024)
}

__global__ void finalize_kernel(int layer, const float* __restrict__ g,
                                const float* __restrict__ bparam, float inv, int C)
{
    int c = threadIdx.x + blockIdx.x*blockDim.x;
    if (c<C){
        double s=0.0, q=0.0;
#pragma unroll 4
        for (int r=0;r<NREP;r++){
            const double* acc = g_accR + (size_t)r*12288 + layer*2048;
            s += acc[c]; q += acc[C+c];
        }
        double mean = s*(double)inv;
        double var  = q*(double)inv - mean*mean;
        float is = rsqrtf((float)var + EPSV)*g[c];
        g_scale[layer*1024+c]=is;
        g_shift[layer*1024+c]=bparam[c]-(float)mean*is;
    }
}

// ---------------- BN+lrelu + transpose (b,n,o) -> (b,o,n) into d_out ----------------
__global__ void final_y_kernel(float* __restrict__ out)
{
    __shared__ float tile[32][33];
    int b = blockIdx.z;
    int n0 = blockIdx.x<<5, o0 = blockIdx.y<<5;
    int tx = threadIdx.x, ty = threadIdx.y;
    float sc = g_scale[5*1024+o0+tx], sh = g_shift[5*1024+o0+tx];
#pragma unroll
    for (int r=0;r<4;r++){
        int n = n0+ty+(r<<3);
        float v = g_ypre[(size_t)(b*NN+n)*1024 + o0+tx]*sc+sh;
        v = v>0.f ? v : 0.2f*v;
        tile[ty+(r<<3)][tx]=v;
    }
    __syncthreads();
#pragma unroll
    for (int r=0;r<4;r++){
        int o = o0+ty+(r<<3);
        out[(size_t)b*NN*1024 + (size_t)o*NN + n0+tx] = tile[tx][ty+(r<<3)];
    }
}

// ---------------- argmax / max over N per (b, channel) ----------------
__global__ void pool_kernel(float* __restrict__ out)
{
    int bo = blockIdx.x;
    const float* row = out + (size_t)bo*NN;
    int tid=threadIdx.x;
    float best=-3.4e38f; int bidx=0x7fffffff;
    for (int n=tid;n<NN;n+=256){
        float v=row[n];
        if (v>best){best=v;bidx=n;}
    }
    __shared__ float sv[256]; __shared__ int si[256];
    sv[tid]=best; si[tid]=bidx;
    __syncthreads();
    for (int s=128;s>0;s>>=1){
        if (tid<s){
            float v2=sv[tid+s]; int i2=si[tid+s];
            if (v2>sv[tid] || (v2==sv[tid] && i2<si[tid])){ sv[tid]=v2; si[tid]=i2; }
        }
        __syncthreads();
    }
    if (tid==0){
        out[(size_t)BB*1024*NN + bo]            = (float)si[0];
        out[(size_t)BB*1024*NN + BB*1024 + bo]  = sv[0];
    }
}

// ---------------- launch ----------------
extern "C" void kernel_launch(void* const* d_in, const int* in_sizes, int n_in,
                              void* d_out, int out_size)
{
    const float* x  = (const float*)d_in[0];
    const float* W1 = (const float*)d_in[1];
    const float* W2 = (const float*)d_in[2];
    const float* W3 = (const float*)d_in[3];
    const float* W4 = (const float*)d_in[4];
    const float* W5 = (const float*)d_in[5];
    const float* W6 = (const float*)d_in[6];
    const float* g1=(const float*)d_in[7];  const float* b1=(const float*)d_in[8];
    const float* g2=(const float*)d_in[9];  const float* b2=(const float*)d_in[10];
    const float* g3=(const float*)d_in[11]; const float* b3=(const float*)d_in[12];
    const float* g4=(const float*)d_in[13]; const float* b4=(const float*)d_in[14];
    const float* g5=(const float*)d_in[15]; const float* b5=(const float*)d_in[16];
    const float* g6=(const float*)d_in[17]; const float* b6=(const float*)d_in[18];
    float* out = (float*)d_out;

    const float invE = 1.0f/(float)NEg;
    const float invR = 1.0f/(float)(BB*NN);
    dim3 kp(NN/128, 4, BB);          // knn phase A grid

    zero_acc_kernel<<<2048,256>>>();                          // 0

    // block 1 (knn_part<3> at captured slot 3)
    sqx_kernel<<<NPTS/256,256>>>(x);                          // 1
    point_gemm3_kernel<<<NPTS/64,256>>>(x, W1, 0, 0);         // 2  Pa1
    knn_part<3><<<kp,128>>>(x, 0, 3*NN, 1, NN);               // 3  <- profiled
    knn_merge<3><<<NPTS/64,256>>>(x, 0, 3*NN, 1, NN);         // 4
    point_gemm3_kernel<<<NPTS/64,256>>>(x, W1, 1, 1);         // 5  Pc1
    center_reduce_kernel<<<NPTS/64,256>>>(0, 0);              //    stats L0
    finalize_kernel<<<1,64>>>(0, g1, b1, invE, 64);
    conv_gather_gemm<<<NEg/128,256>>>(0, 1, W2, 0);           // stats L1 + enc max/min tab0
    finalize_kernel<<<1,64>>>(1, g2, b2, invE, 64);
    maxpool_apply_enc<<<(PTCH+255)/256,256>>>(1, 0, 0);       // -> x1

    // block 2
    sq64_kernel<<<NPTS/128,128>>>(1);
    knn_part<64><<<kp,128>>>(nullptr, 1, NN*64, 64, 1);
    knn_merge<64><<<NPTS/64,256>>>(nullptr, 1, NN*64, 64, 1);
    point_gemm_kernel<<<NPTS/128,256>>>(1, W3, 0, 0);
    point_gemm_kernel<<<NPTS/128,256>>>(1, W3, 1, 1);
    center_reduce_kernel<<<NPTS/64,256>>>(2, 0);              // stats L2
    finalize_kernel<<<1,64>>>(2, g3, b3, invE, 64);
    conv_gather_gemm<<<NEg/128,256>>>(2, 3, W4, 1);           // stats L3 + enc max/min tab1
    finalize_kernel<<<1,64>>>(3, g4, b4, invE, 64);
    maxpool_apply_enc<<<(PTCH+255)/256,256>>>(3, 1, 1);       // -> x2

    // block 3
    sq64_kernel<<<NPTS/128,128>>>(2);
    knn_part<64><<<kp,128>>>(nullptr, 2, NN*64, 64, 1);
    knn_merge<64><<<NPTS/64,256>>>(nullptr, 2, NN*64, 64, 1);
    point_gemm_kernel<<<NPTS/128,256>>>(2, W5, 0, 0);
    point_gemm_kernel<<<NPTS/128,256>>>(2, W5, 1, 1);
    center_reduce_kernel<<<NPTS/64,256>>>(4, 1);              // stats L4 + plain pre max/min
    finalize_kernel<<<1,64>>>(4, g5, b5, invE, 64);
    maxpool_apply_kernel<<<(PTCH+255)/256,256>>>(4);          // -> x3

    // head
    conv6_kernel<<<dim3(NPTS/128,16),256>>>(W6);              // -> ypre, stats L5
    finalize_kernel<<<4,256>>>(5, g6, b6, invR, 1024);
    final_y_kernel<<<dim3(NN/32, 1024/32, BB), dim3(32,8)>>>(out);
    pool_kernel<<<BB*1024,256>>>(out);
}

// round 17
// speedup vs baseline: 1.2220x; 1.0004x over previous
#include <cuda_runtime.h>

#define BB 16
#define NN 2048
#define KK 20
#define KC 26               // phase-A candidate count per subset (margin 6)
#define NEg (BB*NN*KK)      // 655360 edges
#define EPSV 1e-5f
#define NREP 32             // stats accumulator replication factor
#define NPTS (BB*NN)        // 32768 points
#define PTCH (NPTS*64)      // 2097152 entries per table

// ---------------- scratch (static device allocations) ----------------
__device__ float g_tab[12582912];         // enc max/min tables (4 x 2M) + plain pre tables (2 x 2M)
__device__ int   g_idx[NEg];
__device__ unsigned g_scrK[NPTS*4*KC];    // knn phase-A packed keys (sorted desc per subset)
__device__ unsigned g_tau[NPTS];          // warm-start thresholds
__device__ unsigned long long g_pool[BB*1024];  // encoded (max<<32 | 2047-n) per (b,o)
__device__ float g_x1[PTCH];
__device__ float g_x2[PTCH];
__device__ float g_x3[PTCH];
__device__ float g_Pa[PTCH];
__device__ float g_Pc[PTCH];
__device__ float g_sq[NPTS];
__device__ float g_ypre[33554432];        // B*N*1024
__device__ double g_accR[NREP*6*2048];    // replicated per-layer sum/sumsq
__device__ float g_scale[6*1024];
__device__ float g_shift[6*1024];

__device__ __forceinline__ unsigned fenc(float f){
    unsigned b = __float_as_uint(f);
    return (b>>31) ? ~b : (b | 0x80000000u);
}
__device__ __forceinline__ float fdec(unsigned e){
    unsigned b = (e>>31) ? (e ^ 0x80000000u) : ~e;
    return __uint_as_float(b);
}

__global__ void zero_acc_kernel() {
    int i = blockIdx.x*256 + threadIdx.x;
    if (i < NREP*6*2048) g_accR[i] = 0.0;
    if (i < BB*1024) g_pool[i] = 0ull;
    unsigned* t = reinterpret_cast<unsigned*>(g_tab);
    for (int j = i; j < 4*PTCH; j += gridDim.x*256)
        t[j] = ((j>>21)&1) ? 0xFFFFFFFFu : 0u;
}

// squared norms from raw x (B,3,N)
__global__ void sqx_kernel(const float* __restrict__ x){
    int i = blockIdx.x*256 + threadIdx.x;
    if (i < NPTS){
        int b = i >> 11, n = i & (NN-1);
        const float* xb = x + (size_t)b*3*NN;
        float a=xb[n], c=xb[NN+n], d=xb[2*NN+n];
        g_sq[i] = a*a + c*c + d*d;
    }
}

// squared norms from 64-channel point features
__global__ void sq64_kernel(int sel){
    const float* pts = (sel==1) ? g_x1 : g_x2;
    int i = blockIdx.x*128 + threadIdx.x;
    if (i < NPTS){
        const float4* p = reinterpret_cast<const float4*>(pts + ((size_t)i<<6));
        float s = 0.f;
#pragma unroll
        for (int q=0;q<16;q++){
            float4 v = p[q];
            s += v.x*v.x + v.y*v.y + v.z*v.z + v.w*v.w;
        }
        g_sq[i] = s;
    }
}

// ---------------- warm-start: tau0 per query from previous-stage neighbors (C=64 stages) ----------------
__global__ void warm_tau_kernel(int sel)
{
    const float* pts = (sel==1) ? g_x1 : g_x2;
    int qg = blockIdx.x*128 + threadIdx.x;
    if (qg >= NPTS) return;
    int b = qg>>11, row = qg&(NN-1);
    const float* base = pts + (size_t)b*NN*64;
    const float* sqb  = g_sq + (size_t)b*NN;
    float4 pr[16];
    {
        const float4* p4 = reinterpret_cast<const float4*>(base + ((size_t)row<<6));
#pragma unroll
        for (int cq=0;cq<16;cq++) pr[cq]=p4[cq];
    }
    const int* pri = g_idx + (size_t)qg*KK;
    unsigned wmin = 0xFFFFFFFFu;
#pragma unroll 1
    for (int k=0;k<KK;k++){
        int q = pri[k];
        const float4* c4 = reinterpret_cast<const float4*>(base + ((size_t)q<<6));
        float d0=0.f,d1=0.f,d2=0.f,d3=0.f;
#pragma unroll
        for (int cq=0;cq<16;cq++){
            float4 tv = c4[cq];
            d0 += pr[cq].x*tv.x; d1 += pr[cq].y*tv.y;
            d2 += pr[cq].z*tv.z; d3 += pr[cq].w*tv.w;
        }
        float d = 2.f*((d0+d1)+(d2+d3)) - sqb[q];
        unsigned key = (fenc(d) & 0xFFFFF800u) | (unsigned)q;
        wmin = wmin < key ? wmin : key;
    }
    g_tau[qg] = (wmin > (1u<<14)) ? (wmin - (1u<<14)) : 0u;
}

// ---------------- KNN phase A: 4-way split, packed-key top-26, warm threshold ----------------
template<int C>
__global__ void knn_part(const float* __restrict__ ext, int sel, int sB, int sN, int sC, int warm)
{
    const float* pts = (sel==0) ? ext : (sel==1 ? g_x1 : g_x2);
    __shared__ __align__(16) float tile[128][(C==3)?4:68];
    __shared__ float sqs[128];
    int b = blockIdx.z;
    int s = blockIdx.y;
    int row = blockIdx.x*128 + threadIdx.x;
    const float* base = pts + (size_t)b * sB;
    const float* sqb  = g_sq + (size_t)b * NN;

    float p[C];
#pragma unroll
    for (int c=0;c<C;c++) p[c] = base[(size_t)row*sN + (size_t)c*sC];

    unsigned bd[KC];
#pragma unroll
    for (int i=0;i<KC;i++) bd[i]=0u;
    unsigned tau0 = warm ? g_tau[b*NN+row] : 0u;
    unsigned worst = tau0;

    int t0 = s*512;
    for (int t=t0; t<t0+512; t+=128) {
        __syncthreads();
        if (C==3) {
            for (int i=threadIdx.x;i<128*3;i+=128){
                int c=i>>7, col=i&127;
                tile[col][c] = base[(size_t)(t+col)*sN + (size_t)c*sC];
            }
        } else {
            const float4* b4 = reinterpret_cast<const float4*>(base);
            for (int i=threadIdx.x;i<128*(C/4);i+=128){
                int col=i>>4, cq=i&15;
                *reinterpret_cast<float4*>(&tile[col][cq<<2]) =
                    b4[((size_t)(t+col)<<4)+cq];
            }
        }
        sqs[threadIdx.x] = sqb[t+threadIdx.x];
        __syncthreads();
#pragma unroll 1
        for (int j=0;j<128;j++) {
            float d;
            if (C==3) {
                d = 2.f*(p[0]*tile[j][0]+p[1]*tile[j][1]+p[2]*tile[j][2]) - sqs[j];
            } else {
                float d0=0.f,d1=0.f,d2=0.f,d3=0.f;
#pragma unroll
                for (int cq=0;cq<C/4;cq++){
                    float4 tv = *reinterpret_cast<const float4*>(&tile[j][cq*4]);
                    d0 += p[cq*4+0]*tv.x; d1 += p[cq*4+1]*tv.y;
                    d2 += p[cq*4+2]*tv.z; d3 += p[cq*4+3]*tv.w;
                }
                d = 2.f*((d0+d1)+(d2+d3)) - sqs[j];
            }
            unsigned key = (fenc(d) & 0xFFFFF800u) | (unsigned)(t + j);
            if (key > worst) {
                unsigned tmp = key;
#pragma unroll
                for (int ss=0; ss<KC; ss++){
                    unsigned hi = bd[ss] > tmp ? bd[ss] : tmp;
                    unsigned lo = bd[ss] > tmp ? tmp : bd[ss];
                    bd[ss] = hi; tmp = lo;
                }
                worst = bd[KC-1] > tau0 ? bd[KC-1] : tau0;
            }
        }
    }
    unsigned* oK = g_scrK + ((size_t)(b*NN+row)*4 + s)*KC;
#pragma unroll
    for (int i=0;i<KC;i++) oK[i]=bd[i];
}

// ---------------- KNN merge: rank union of 4 sorted key lists, fp64 rerank -> top-20 set ----------------
template<int C>
__global__ void __launch_bounds__(256) knn_merge(const float* __restrict__ ext,
                                                 int sel, int sB, int sN, int sC)
{
    const float* pts = (sel==0) ? ext : (sel==1 ? g_x1 : g_x2);
    __shared__ unsigned sc[64][104];
    __shared__ unsigned ssel[64][26];
    __shared__ double dval[64][26];
    int tid = threadIdx.x;
    int s  = tid & 3;
    int ql = tid >> 2;
    int qg = blockIdx.x*64 + ql;
    int b  = qg >> 11;
    int row = qg & (NN-1);

    {
        const unsigned* iK = g_scrK + ((size_t)qg*4 + s)*KC;
#pragma unroll
        for (int i=0;i<KC;i++) sc[ql][s*KC+i] = iK[i];
    }
    // pre-init rank slots (zero-pads from warm mode leave gaps)
    {
        int base_i = s*7;
#pragma unroll
        for (int i=0;i<7;i++){ int r=base_i+i; if (r<KC) ssel[ql][r]=0u; }
    }
    __syncthreads();

    // rank each own nonzero item within the 104-union (keys unique: strict compare)
    {
        int os0=(s+1)&3, os1=(s+2)&3, os2=(s+3)&3;
        int q0=0,q1=0,q2=0;
#pragma unroll 1
        for (int i=0;i<KC;i++){
            unsigned m = sc[ql][s*KC+i];
            if (m == 0u) break;
            while (q0<KC && sc[ql][os0*KC+q0] > m) q0++;
            while (q1<KC && sc[ql][os1*KC+q1] > m) q1++;
            while (q2<KC && sc[ql][os2*KC+q2] > m) q2++;
            int rank = i + q0 + q1 + q2;
            if (rank < KC) ssel[ql][rank] = m;
        }
    }
    __syncthreads();

    // fp64 rescore the survivors (4 lanes/query, strided); zero slots -> sentinel
    const float* base = pts + (size_t)b * sB;
#pragma unroll 1
    for (int r=s; r<KC; r+=4){
        unsigned kk = ssel[ql][r];
        if (kk != 0u){
            int cand = (int)(kk & 2047u);
            double dot=0.0, qsq=0.0;
#pragma unroll 4
            for (int c=0;c<C;c++){
                double qv = (double)base[(size_t)cand*sN + (size_t)c*sC];
                double pv = (double)base[(size_t)row*sN + (size_t)c*sC];
                dot = fma(pv, qv, dot);
                qsq = fma(qv, qv, qsq);
            }
            dval[ql][r] = 2.0*dot - qsq;
            ssel[ql][r] = (unsigned)cand;
        } else {
            dval[ql][r] = -1.0e300;
            ssel[ql][r] = 0x40000000u + (unsigned)r;   // unique, ranks last
        }
    }
    __syncthreads();

    // exact top-20 set by fp64 rank count
#pragma unroll 1
    for (int r=s; r<KC; r+=4){
        double di = dval[ql][r]; int ii = (int)ssel[ql][r];
        int cnt = 0;
#pragma unroll 1
        for (int r2=0;r2<KC;r2++){
            double dk = dval[ql][r2]; int ik = (int)ssel[ql][r2];
            bool gt = (dk > di) || (dk == di && ik < ii);
            cnt += gt ? 1 : 0;
        }
        if (cnt < KK) g_idx[(size_t)qg*KK + cnt] = ii;
    }
}

__device__ __forceinline__ float lrelu(float v){ return v>0.f ? v : 0.2f*v; }

// ---------------- point GEMM from raw x (B,3,N): 3 -> 64 ----------------
__global__ void point_gemm3_kernel(const float* __restrict__ x, const float* __restrict__ W1,
                                   int mode, int out_sel)
{
    __shared__ float w[64][3];
    int tid = threadIdx.x;
    if (tid < 192){
        int o = tid/3, c = tid - o*3;
        w[o][c] = mode ? (W1[o*6+3+c] - W1[o*6+c]) : W1[o*6+c];
    }
    __syncthreads();
    int i = blockIdx.x*64 + (tid>>2);
    int og = tid & 3;
    int b = i>>11, n = i & (NN-1);
    const float* xb = x + (size_t)b*3*NN;
    float x0=xb[n], x1v=xb[NN+n], x2v=xb[2*NN+n];
    float* outp = (out_sel ? g_Pc : g_Pa) + ((size_t)i<<6) + og*16;
#pragma unroll
    for (int oo=0;oo<16;oo+=4){
        int ob = og*16+oo;
        float4 v;
        v.x = x0*w[ob+0][0] + x1v*w[ob+0][1] + x2v*w[ob+0][2];
        v.y = x0*w[ob+1][0] + x1v*w[ob+1][1] + x2v*w[ob+1][2];
        v.z = x0*w[ob+2][0] + x1v*w[ob+2][1] + x2v*w[ob+2][2];
        v.w = x0*w[ob+3][0] + x1v*w[ob+3][1] + x2v*w[ob+3][2];
        *reinterpret_cast<float4*>(outp+oo) = v;
    }
}

#define MMA8x4(a0,a1,b) \
    acc[0][0]+=a0.x*b.x; acc[0][1]+=a0.x*b.y; acc[0][2]+=a0.x*b.z; acc[0][3]+=a0.x*b.w; \
    acc[1][0]+=a0.y*b.x; acc[1][1]+=a0.y*b.y; acc[1][2]+=a0.y*b.z; acc[1][3]+=a0.y*b.w; \
    acc[2][0]+=a0.z*b.x; acc[2][1]+=a0.z*b.y; acc[2][2]+=a0.z*b.z; acc[2][3]+=a0.z*b.w; \
    acc[3][0]+=a0.w*b.x; acc[3][1]+=a0.w*b.y; acc[3][2]+=a0.w*b.z; acc[3][3]+=a0.w*b.w; \
    acc[4][0]+=a1.x*b.x; acc[4][1]+=a1.x*b.y; acc[4][2]+=a1.x*b.z; acc[4][3]+=a1.x*b.w; \
    acc[5][0]+=a1.y*b.x; acc[5][1]+=a1.y*b.y; acc[5][2]+=a1.y*b.z; acc[5][3]+=a1.y*b.w; \
    acc[6][0]+=a1.z*b.x; acc[6][1]+=a1.z*b.y; acc[6][2]+=a1.z*b.z; acc[6][3]+=a1.z*b.w; \
    acc[7][0]+=a1.w*b.x; acc[7][1]+=a1.w*b.y; acc[7][2]+=a1.w*b.z; acc[7][3]+=a1.w*b.w;

#define STATS_EPILOGUE(accL, base_off, Cn) \
    { \
        float4 sv, qv_; \
        { float s0=0,s1=0,s2=0,s3=0,q0=0,q1=0,q2=0,q3=0; \
          _Pragma("unroll") \
          for (int j=0;j<8;j++){ \
              float v0=acc[j][0],v1=acc[j][1],v2=acc[j][2],v3=acc[j][3]; \
              s0+=v0;s1+=v1;s2+=v2;s3+=v3; q0+=v0*v0;q1+=v1*v1;q2+=v2*v2;q3+=v3*v3; } \
          sv=make_float4(s0,s1,s2,s3); qv_=make_float4(q0,q1,q2,q3); } \
        sps4[ty][tx]=sv; spq4[ty][tx]=qv_; \
        __syncthreads(); \
        if (tid < 64){ \
            const float* fs_=reinterpret_cast<const float*>(sps4); \
            const float* fq_=reinterpret_cast<const float*>(spq4); \
            double s=0.0,q=0.0; \
            _Pragma("unroll") \
            for (int j=0;j<16;j++){ s+=(double)fs_[j*64+tid]; q+=(double)fq_[j*64+tid]; } \
            double* accp = g_accR + (size_t)(blockIdx.x & (NREP-1))*12288 + (accL)*2048; \
            atomicAdd(&accp[(base_off) + tid],        s); \
            atomicAdd(&accp[(Cn) + (base_off) + tid], q); \
        } \
    }

// ---------------- gather GEMM: A=lrelu(BN(Pa[nbr]+Pc[cen])), fused stats + per-center max/min ----------------
__global__ void conv_gather_gemm(int bn_layer, int stat_layer, const float* __restrict__ W, int tab)
{
    __shared__ __align__(16) float As[32][132];
    __shared__ __align__(16) float Ws[64][68];
    __shared__ __align__(16) float4 s_sc[16], s_sh[16];
    __shared__ __align__(16) float4 sps4[16][16], spq4[16][16];
    __shared__ int s_cen[128], s_nbr[128];
    int tid = threadIdx.x;
    int eb = blockIdx.x*128;
    if (tid < 16){
        s_sc[tid] = reinterpret_cast<const float4*>(g_scale + bn_layer*1024)[tid];
        s_sh[tid] = reinterpret_cast<const float4*>(g_shift + bn_layer*1024)[tid];
    }
    if (tid < 128){
        int e = eb+tid;
        int bn = e/KK;
        s_cen[tid]=bn;
        s_nbr[tid]=(bn & ~(NN-1)) + g_idx[e];
    }
    {
        const float4* w4 = reinterpret_cast<const float4*>(W);
#pragma unroll 2
        for (int i=tid;i<1024;i+=256){
            int o=i>>4, kq=i&15; int kk=kq<<2;
            float4 w = w4[i];
            Ws[kk][o]=w.x; Ws[kk+1][o]=w.y; Ws[kk+2][o]=w.z; Ws[kk+3][o]=w.w;
        }
    }
    int tx=tid&15, ty=tid>>4;
    float acc[8][4];
#pragma unroll
    for (int j=0;j<8;j++){
#pragma unroll
        for (int i=0;i<4;i++) acc[j][i]=0.f;
    }
    const float4* Pa4 = reinterpret_cast<const float4*>(g_Pa);
    const float4* Pc4 = reinterpret_cast<const float4*>(g_Pc);
#pragma unroll 1
    for (int chunk=0; chunk<2; chunk++){
        __syncthreads();
#pragma unroll 2
        for (int i=tid;i<1024;i+=256){
            int e=i>>3, kq=i&7;
            int kg=(chunk<<3)+kq;
            float4 a = Pa4[((size_t)s_nbr[e]<<4)+kg];
            float4 c = Pc4[((size_t)s_cen[e]<<4)+kg];
            float4 sc=s_sc[kg], sh=s_sh[kg];
            int kk=kq<<2;
            As[kk  ][e]=lrelu((a.x+c.x)*sc.x+sh.x);
            As[kk+1][e]=lrelu((a.y+c.y)*sc.y+sh.y);
            As[kk+2][e]=lrelu((a.z+c.z)*sc.z+sh.z);
            As[kk+3][e]=lrelu((a.w+c.w)*sc.w+sh.w);
        }
        __syncthreads();
        int kb = chunk<<5;
#pragma unroll 8
        for (int k=0;k<32;k++){
            float4 a0 = *reinterpret_cast<const float4*>(&As[k][ty<<3]);
            float4 a1 = *reinterpret_cast<const float4*>(&As[k][(ty<<3)+4]);
            float4 b  = *reinterpret_cast<const float4*>(&Ws[kb+k][tx<<2]);
            MMA8x4(a0,a1,b)
        }
    }
    __syncthreads();
    STATS_EPILOGUE(stat_layer, 0, 64)

    unsigned* encMax = reinterpret_cast<unsigned*>(g_tab) + (size_t)tab*2*PTCH;
    unsigned* encMin = encMax + PTCH;
    int c0 = eb/KK;
#pragma unroll 1
    for (int chunk=0; chunk<2; chunk++){
        __syncthreads();
        if ((tx>>3)==chunk){
            int cb = (tx&7)<<2;
#pragma unroll
            for (int j=0;j<8;j++){
#pragma unroll
                for (int i=0;i<4;i++) As[cb+i][(ty<<3)+j] = acc[j][i];
            }
        }
        __syncthreads();
        int ch = tid & 31, cslot = tid>>5;
        int ci = c0 + cslot;
        int lo = ci*KK - eb;     if (lo<0)  lo=0;
        int hi = ci*KK+KK - eb;  if (hi>128) hi=128;
        if (lo < hi && ci < NPTS){
            float m=-3.4e38f, mn=3.4e38f;
            for (int e=lo;e<hi;e++){
                float v = As[ch][e];
                m = fmaxf(m,v); mn = fminf(mn,v);
            }
            atomicMax(&encMax[(size_t)ci*64 + (chunk<<5) + ch], fenc(m));
            atomicMin(&encMin[(size_t)ci*64 + (chunk<<5) + ch], fenc(mn));
        }
    }
}

// ---------------- point GEMM (64ch): P = pts @ Wa^T (mode 0) or pts @ (Wb-Wa)^T (mode 1) ----------------
__global__ void point_gemm_kernel(int sel_pts, const float* __restrict__ W, int mode, int out_sel)
{
    const float* pts = sel_pts==1 ? g_x1 : g_x2;
    float* outp = out_sel==0 ? g_Pa : g_Pc;
    __shared__ __align__(16) float As[32][132];
    __shared__ __align__(16) float Ws[64][68];
    int tid = threadIdx.x;
    int pb = blockIdx.x*128;
    {
        const float4* w4 = reinterpret_cast<const float4*>(W);
#pragma unroll 2
        for (int i=tid;i<1024;i+=256){
            int o=i>>4, kq=i&15; int kk=kq<<2;
            float4 w;
            if (mode){
                float4 wb = w4[(o<<5) + 16 + kq];
                float4 wa = w4[(o<<5) + kq];
                w = make_float4(wb.x-wa.x, wb.y-wa.y, wb.z-wa.z, wb.w-wa.w);
            } else {
                w = w4[(o<<5) + kq];
            }
            Ws[kk][o]=w.x; Ws[kk+1][o]=w.y; Ws[kk+2][o]=w.z; Ws[kk+3][o]=w.w;
        }
    }
    int tx=tid&15, ty=tid>>4;
    float acc[8][4];
#pragma unroll
    for (int j=0;j<8;j++){
#pragma unroll
        for (int i=0;i<4;i++) acc[j][i]=0.f;
    }
    const float4* h4 = reinterpret_cast<const float4*>(pts + ((size_t)pb<<6));
#pragma unroll 1
    for (int chunk=0; chunk<2; chunk++){
        __syncthreads();
#pragma unroll 2
        for (int i=tid;i<1024;i+=256){
            int e=i>>3, kq=i&7;
            int kg=(chunk<<3)+kq;
            float4 v = h4[(e<<4)+kg];
            int kk=kq<<2;
            As[kk][e]=v.x; As[kk+1][e]=v.y; As[kk+2][e]=v.z; As[kk+3][e]=v.w;
        }
        __syncthreads();
        int kb = chunk<<5;
#pragma unroll 8
        for (int k=0;k<32;k++){
            float4 a0 = *reinterpret_cast<const float4*>(&As[k][ty<<3]);
            float4 a1 = *reinterpret_cast<const float4*>(&As[k][(ty<<3)+4]);
            float4 b  = *reinterpret_cast<const float4*>(&Ws[kb+k][tx<<2]);
            MMA8x4(a0,a1,b)
        }
    }
#pragma unroll
    for (int j=0;j<8;j++){
        float4 v = make_float4(acc[j][0],acc[j][1],acc[j][2],acc[j][3]);
        *reinterpret_cast<float4*>(&outp[((size_t)(pb+(ty<<3)+j)<<6)+(tx<<2)]) = v;
    }
}

// ---------------- center reduce: stats (+optional pre-BN max/min) from Pa/Pc ----------------
__global__ void center_reduce_kernel(int stat_layer, int write_pre)
{
    __shared__ int s_idx[64*KK];
    __shared__ float fs[64][68];
    __shared__ float fq[64][68];
    __shared__ float pfold[2][256];
    int tid = threadIdx.x;
    int nb = blockIdx.x*64;
    for (int i=tid;i<64*KK;i+=256) s_idx[i] = g_idx[(size_t)nb*KK + i];
    __syncthreads();
    int cen_l = tid>>2, cq = tid&3;
    int bn = nb + cen_l;
    int base = bn & ~(NN-1);
    const float4* Pa4 = reinterpret_cast<const float4*>(g_Pa);
    const float4* Pc4 = reinterpret_cast<const float4*>(g_Pc);
    float4 S1[4], S2[4], Mx[4], Mn[4];
#pragma unroll
    for (int i=0;i<4;i++){
        S1[i]=make_float4(0,0,0,0); S2[i]=make_float4(0,0,0,0);
        Mx[i]=make_float4(-3.4e38f,-3.4e38f,-3.4e38f,-3.4e38f);
        Mn[i]=make_float4( 3.4e38f, 3.4e38f, 3.4e38f, 3.4e38f);
    }
#pragma unroll 1
    for (int k=0;k<KK;k++){
        size_t idx = (size_t)(base + s_idx[cen_l*KK+k]);
        const float4* r = Pa4 + (idx<<4) + (cq<<2);
#pragma unroll
        for (int i=0;i<4;i++){
            float4 v = r[i];
            S1[i].x+=v.x; S1[i].y+=v.y; S1[i].z+=v.z; S1[i].w+=v.w;
            S2[i].x+=v.x*v.x; S2[i].y+=v.y*v.y; S2[i].z+=v.z*v.z; S2[i].w+=v.w*v.w;
            Mx[i].x=fmaxf(Mx[i].x,v.x); Mx[i].y=fmaxf(Mx[i].y,v.y);
            Mx[i].z=fmaxf(Mx[i].z,v.z); Mx[i].w=fmaxf(Mx[i].w,v.w);
            Mn[i].x=fminf(Mn[i].x,v.x); Mn[i].y=fminf(Mn[i].y,v.y);
            Mn[i].z=fminf(Mn[i].z,v.z); Mn[i].w=fminf(Mn[i].w,v.w);
        }
    }
    const float4* pr = Pc4 + ((size_t)bn<<4) + (cq<<2);
    float* preMax = g_tab + 4*PTCH;
    float* preMin = g_tab + 5*PTCH;
#pragma unroll
    for (int i=0;i<4;i++){
        float4 c = pr[i];
        float4 s4v, q4v;
        s4v.x = S1[i].x + 20.f*c.x;  q4v.x = S2[i].x + 2.f*c.x*S1[i].x + 20.f*c.x*c.x;
        s4v.y = S1[i].y + 20.f*c.y;  q4v.y = S2[i].y + 2.f*c.y*S1[i].y + 20.f*c.y*c.y;
        s4v.z = S1[i].z + 20.f*c.z;  q4v.z = S2[i].z + 2.f*c.z*S1[i].z + 20.f*c.z*c.z;
        s4v.w = S1[i].w + 20.f*c.w;  q4v.w = S2[i].w + 2.f*c.w*S1[i].w + 20.f*c.w*c.w;
        int cbase = (cq<<4) + (i<<2);
        fs[cen_l][cbase+0]=s4v.x; fs[cen_l][cbase+1]=s4v.y; fs[cen_l][cbase+2]=s4v.z; fs[cen_l][cbase+3]=s4v.w;
        fq[cen_l][cbase+0]=q4v.x; fq[cen_l][cbase+1]=q4v.y; fq[cen_l][cbase+2]=q4v.z; fq[cen_l][cbase+3]=q4v.w;
        if (write_pre){
            float4 mx = make_float4(Mx[i].x+c.x, Mx[i].y+c.y, Mx[i].z+c.z, Mx[i].w+c.w);
            float4 mn = make_float4(Mn[i].x+c.x, Mn[i].y+c.y, Mn[i].z+c.z, Mn[i].w+c.w);
            *reinterpret_cast<float4*>(preMax + ((size_t)bn<<6) + cbase) = mx;
            *reinterpret_cast<float4*>(preMin + ((size_t)bn<<6) + cbase) = mn;
        }
    }
    __syncthreads();
    {
        int ch = tid & 63, grp = tid>>6;
        float s=0.f,q=0.f;
#pragma unroll
        for (int i=0;i<16;i++){ s+=fs[grp*16+i][ch]; q+=fq[grp*16+i][ch]; }
        pfold[0][tid]=s; pfold[1][tid]=q;
    }
    __syncthreads();
    if (tid<64){
        double S = (double)pfold[0][tid]+pfold[0][64+tid]+pfold[0][128+tid]+pfold[0][192+tid];
        double Q = (double)pfold[1][tid]+pfold[1][64+tid]+pfold[1][128+tid]+pfold[1][192+tid];
        double* accp = g_accR + (size_t)(blockIdx.x & (NREP-1))*12288 + stat_layer*2048;
        atomicAdd(&accp[tid],    S);
        atomicAdd(&accp[64+tid], Q);
    }
}

// ---------------- BN-apply on encoded max/min tables -> x1/x2 ----------------
__global__ void maxpool_apply_enc(int layer, int tab, int out_sel)
{
    int i = blockIdx.x*256 + threadIdx.x;
    if (i < PTCH){
        int c = i & 63;
        float sc = g_scale[layer*1024+c], sh = g_shift[layer*1024+c];
        const unsigned* base = reinterpret_cast<const unsigned*>(g_tab) + (size_t)tab*2*PTCH;
        unsigned e = (sc >= 0.f) ? base[i] : base[PTCH + i];
        float v = fdec(e)*sc + sh;
        float* outp = out_sel==0 ? g_x1 : g_x2;
        outp[i] = v>0.f ? v : 0.2f*v;
    }
}

// ---------------- BN-apply on plain pre tables -> x3 (block 3) ----------------
__global__ void maxpool_apply_kernel(int layer)
{
    int i = blockIdx.x*256 + threadIdx.x;
    if (i < PTCH){
        int c = i & 63;
        float sc = g_scale[layer*1024+c], sh = g_shift[layer*1024+c];
        float pre = (sc >= 0.f) ? g_tab[4*PTCH + i] : g_tab[5*PTCH + i];
        float v = pre*sc + sh;
        g_x3[i] = v>0.f ? v : 0.2f*v;
    }
}

// ---------------- conv6: cat[x1,x2,x3] (192) -> 1024, fused stats ----------------
__global__ void conv6_kernel(const float* __restrict__ W6)
{
    __shared__ __align__(16) float As[32][132];
    __shared__ __align__(16) float Ws[64][68];
    __shared__ __align__(16) float4 sps4[16][16], spq4[16][16];
    int tid=threadIdx.x;
    int rb = blockIdx.x*128;
    int ob = blockIdx.y*64;
    int tx=tid&15, ty=tid>>4;
    float acc[8][4];
#pragma unroll
    for (int j=0;j<8;j++){
#pragma unroll
        for (int i=0;i<4;i++) acc[j][i]=0.f;
    }
    const float4* w4 = reinterpret_cast<const float4*>(W6);
#pragma unroll 1
    for (int t=0;t<3;t++){
        const float* src = (t==0)? g_x1 : (t==1)? g_x2 : g_x3;
        const float4* s4 = reinterpret_cast<const float4*>(src + ((size_t)rb<<6));
        __syncthreads();
#pragma unroll 2
        for (int i=tid;i<1024;i+=256){
            int o=i>>4, kq=i&15; int kk=kq<<2;
            float4 w = w4[(size_t)(ob+o)*48 + (t<<4) + kq];
            Ws[kk][o]=w.x; Ws[kk+1][o]=w.y; Ws[kk+2][o]=w.z; Ws[kk+3][o]=w.w;
        }
#pragma unroll 1
        for (int chunk=0; chunk<2; chunk++){
            if (chunk) __syncthreads();
#pragma unroll 2
            for (int i=tid;i<1024;i+=256){
                int e=i>>3, kq=i&7;
                int kg=(chunk<<3)+kq;
                float4 v = s4[(e<<4)+kg];
                int kk=kq<<2;
                As[kk][e]=v.x; As[kk+1][e]=v.y; As[kk+2][e]=v.z; As[kk+3][e]=v.w;
            }
            __syncthreads();
            int kb = chunk<<5;
#pragma unroll 8
            for (int k=0;k<32;k++){
                float4 a0 = *reinterpret_cast<const float4*>(&As[k][ty<<3]);
                float4 a1 = *reinterpret_cast<const float4*>(&As[k][(ty<<3)+4]);
                float4 b  = *reinterpret_cast<const float4*>(&Ws[kb+k][tx<<2]);
                MMA8x4(a0,a1,b)
            }
        }
    }
#pragma unroll
    for (int j=0;j<8;j++){
        float4 v = make_float4(acc[j][0],acc[j][1],acc[j][2],acc[j][3]);
        *reinterpret_cast<float4*>(&g_ypre[(size_t)(rb+(ty<<3)+j)*1024 + ob + (tx<<2)]) = v;
    }
    __syncthreads();
    STATS_EPILOGUE(5, ob, 1024)
}

__global__ void finalize_kernel(int layer, const float* __restrict__ g,
                                const float* __restrict__ bparam, float inv, int C)
{
    int c = threadIdx.x + blockIdx.x*blockDim.x;
    if (c<C){
        double s=0.0, q=0.0;
#pragma unroll 4
        for (int r=0;r<NREP;r++){
            const double* acc = g_accR + (size_t)r*12288 + layer*2048;
            s += acc[c]; q += acc[C+c];
        }
        double mean = s*(double)inv;
        double var  = q*(double)inv - mean*mean;
        float is = rsqrtf((float)var + EPSV)*g[c];
        g_scale[layer*1024+c]=is;
        g_shift[layer*1024+c]=bparam[c]-(float)mean*is;
    }
}

// ---------------- BN+lrelu + transpose into d_out + fused warp argmax -> g_pool ----------------
__global__ void final_y_kernel(float* __restrict__ out)
{
    __shared__ float tile[32][33];
    int b = blockIdx.z;
    int n0 = blockIdx.x<<5, o0 = blockIdx.y<<5;
    int tx = threadIdx.x, ty = threadIdx.y;
    float sc = g_scale[5*1024+o0+tx], sh = g_shift[5*1024+o0+tx];
#pragma unroll
    for (int r=0;r<4;r++){
        int n = n0+ty+(r<<3);
        float v = g_ypre[(size_t)(b*NN+n)*1024 + o0+tx]*sc+sh;
        v = v>0.f ? v : 0.2f*v;
        tile[ty+(r<<3)][tx]=v;
    }
    __syncthreads();
#pragma unroll
    for (int r=0;r<4;r++){
        int o = o0+ty+(r<<3);
        float v = tile[tx][ty+(r<<3)];
        out[(size_t)b*NN*1024 + (size_t)o*NN + n0+tx] = v;
        // warp argmax over tx (n-dimension), tie -> smaller n
        float mv = v; int mn = n0+tx;
#pragma unroll
        for (int off=16; off; off>>=1){
            float v2 = __shfl_down_sync(0xFFFFFFFFu, mv, off);
            int   n2 = __shfl_down_sync(0xFFFFFFFFu, mn, off);
            if (v2 > mv || (v2 == mv && n2 < mn)){ mv=v2; mn=n2; }
        }
        if (tx == 0){
            unsigned long long e = ((unsigned long long)fenc(mv)<<32) | (unsigned)(NN-1-mn);
            atomicMax(&g_pool[b*1024 + o], e);
        }
    }
}

// ---------------- decode pooled max/argmax ----------------
__global__ void pool_finalize(float* __restrict__ out)
{
    int i = blockIdx.x*256 + threadIdx.x;
    if (i < BB*1024){
        unsigned long long e = g_pool[i];
        unsigned hi = (unsigned)(e>>32), lo = (unsigned)(e & 0xFFFFFFFFu);
        out[(size_t)BB*1024*NN + i]            = (float)(NN-1-(int)lo);
        out[(size_t)BB*1024*NN + BB*1024 + i]  = fdec(hi);
    }
}

// ---------------- launch ----------------
extern "C" void kernel_launch(void* const* d_in, const int* in_sizes, int n_in,
                              void* d_out, int out_size)
{
    const float* x  = (const float*)d_in[0];
    const float* W1 = (const float*)d_in[1];
    const float* W2 = (const float*)d_in[2];
    const float* W3 = (const float*)d_in[3];
    const float* W4 = (const float*)d_in[4];
    const float* W5 = (const float*)d_in[5];
    const float* W6 = (const float*)d_in[6];
    const float* g1=(const float*)d_in[7];  const float* b1=(const float*)d_in[8];
    const float* g2=(const float*)d_in[9];  const float* b2=(const float*)d_in[10];
    const float* g3=(const float*)d_in[11]; const float* b3=(const float*)d_in[12];
    const float* g4=(const float*)d_in[13]; const float* b4=(const float*)d_in[14];
    const float* g5=(const float*)d_in[15]; const float* b5=(const float*)d_in[16];
    const float* g6=(const float*)d_in[17]; const float* b6=(const float*)d_in[18];
    float* out = (float*)d_out;

    const float invE = 1.0f/(float)NEg;
    const float invR = 1.0f/(float)(BB*NN);
    dim3 kp(NN/128, 4, BB);          // knn phase A grid

    zero_acc_kernel<<<2048,256>>>();                          // 0

    // block 1 (knn_part<3> at captured slot 3)
    sqx_kernel<<<NPTS/256,256>>>(x);                          // 1
    point_gemm3_kernel<<<NPTS/64,256>>>(x, W1, 0, 0);         // 2  Pa1
    knn_part<3><<<kp,128>>>(x, 0, 3*NN, 1, NN, 0);            // 3  <- profiled
    knn_merge<3><<<NPTS/64,256>>>(x, 0, 3*NN, 1, NN);         // 4
    point_gemm3_kernel<<<NPTS/64,256>>>(x, W1, 1, 1);         // 5  Pc1
    center_reduce_kernel<<<NPTS/64,256>>>(0, 0);              //    stats L0
    finalize_kernel<<<1,64>>>(0, g1, b1, invE, 64);
    conv_gather_gemm<<<NEg/128,256>>>(0, 1, W2, 0);           // stats L1 + enc max/min tab0
    finalize_kernel<<<1,64>>>(1, g2, b2, invE, 64);
    maxpool_apply_enc<<<(PTCH+255)/256,256>>>(1, 0, 0);       // -> x1

    // block 2 (warm-started knn)
    sq64_kernel<<<NPTS/128,128>>>(1);
    warm_tau_kernel<<<NPTS/128,128>>>(1);                     // tau from stage-1 graph
    knn_part<64><<<kp,128>>>(nullptr, 1, NN*64, 64, 1, 1);
    knn_merge<64><<<NPTS/64,256>>>(nullptr, 1, NN*64, 64, 1);
    point_gemm_kernel<<<NPTS/128,256>>>(1, W3, 0, 0);
    point_gemm_kernel<<<NPTS/128,256>>>(1, W3, 1, 1);
    center_reduce_kernel<<<NPTS/64,256>>>(2, 0);              // stats L2
    finalize_kernel<<<1,64>>>(2, g3, b3, invE, 64);
    conv_gather_gemm<<<NEg/128,256>>>(2, 3, W4, 1);           // stats L3 + enc max/min tab1
    finalize_kernel<<<1,64>>>(3, g4, b4, invE, 64);
    maxpool_apply_enc<<<(PTCH+255)/256,256>>>(3, 1, 1);       // -> x2

    // block 3 (warm-started knn)
    sq64_kernel<<<NPTS/128,128>>>(2);
    warm_tau_kernel<<<NPTS/128,128>>>(2);                     // tau from stage-2 graph
    knn_part<64><<<kp,128>>>(nullptr, 2, NN*64, 64, 1, 1);
    knn_merge<64><<<NPTS/64,256>>>(nullptr, 2, NN*64, 64, 1);
    point_gemm_kernel<<<NPTS/128,256>>>(2, W5, 0, 0);
    point_gemm_kernel<<<NPTS/128,256>>>(2, W5, 1, 1);
    center_reduce_kernel<<<NPTS/64,256>>>(4, 1);              // stats L4 + plain pre max/min
    finalize_kernel<<<1,64>>>(4, g5, b5, invE, 64);
    maxpool_apply_kernel<<<(PTCH+255)/256,256>>>(4);          // -> x3

    // head
    conv6_kernel<<<dim3(NPTS/128,16),256>>>(W6);              // -> ypre, stats L5
    finalize_kernel<<<4,256>>>(5, g6, b6, invR, 1024);
    final_y_kernel<<<dim3(NN/32, 1024/32, BB), dim3(32,8)>>>(out);
    pool_finalize<<<64,256>>>(out);
}